// round 15
// baseline (speedup 1.0000x reference)
#include <cuda_runtime.h>
#include <cuda_bf16.h>
#include <math.h>

// ---------------------------------------------------------------------------
// Problem constants
// ---------------------------------------------------------------------------
#define BATCH 8
#define NTOK 4096
#define ROWS (BATCH*NTOK)
#define DIMC 180
#define HEADS 6
#define HD 30
#define QKVW 540
#define MTOK 64
#define RDIM 10
#define GS 128
#define NG 32
#define WS 16
#define WINN 256
#define NWIN 128
#define MLP_HID 360
#define DTD 64
#define CFF 424
#define HH 64
#define WW 64

// bf16 weight scratch offsets (elements)
#define WT_QKV 0
#define WT_ACA (WT_QKV + DIMC*QKVW)
#define WT_WIN (WT_ACA + DIMC*DIMC)
#define WT_FC1 (WT_WIN + DIMC*DIMC)
#define WT_FC2 (WT_FC1 + DIMC*MLP_HID)
#define WT_TOTAL (WT_FC2 + CFF*DIMC)

// ---------------------------------------------------------------------------
// Scratch
// ---------------------------------------------------------------------------
__device__ unsigned short g_xn  [ROWS*DIMC];        // bf16
__device__ float g_qkv  [ROWS*QKVW];
__device__ float g_qatd [ROWS*RDIM];
__device__ float g_kkn  [BATCH*MTOK*RDIM];
__device__ unsigned short g_vvt [BATCH*DIMC*MTOK];  // bf16, transposed [b][n][m]
__device__ float g_tdpr [BATCH*MTOK*DTD];
__device__ unsigned short g_patd[ROWS*MTOK];        // bf16
__device__ int   g_tkid [ROWS];
__device__ int   g_sidx [ROWS];
__device__ unsigned short g_yaca[ROWS*DIMC];        // bf16
__device__ unsigned short g_ywin[ROWS*DIMC];        // bf16
__device__ float g_xsum [ROWS*DIMC];
__device__ unsigned short g_x2n [ROWS*DIMC];        // bf16
__device__ unsigned short g_hc  [ROWS*CFF];         // bf16 (was fp32)
__device__ unsigned short g_hc2 [ROWS*CFF];         // bf16
__device__ float g_wbias[HEADS*WINN*WINN];
__device__ unsigned short g_wt  [WT_TOTAL];         // bf16 transposed weights

// ---------------------------------------------------------------------------
// Helpers
// ---------------------------------------------------------------------------
__device__ __forceinline__ float warp_sum(float v) {
    #pragma unroll
    for (int o = 16; o; o >>= 1) v += __shfl_xor_sync(0xffffffffu, v, o);
    return v;
}
__device__ __forceinline__ float gelu_exact(float v) {
    return 0.5f * v * (1.0f + erff(v * 0.70710678118654752440f));
}
__device__ __forceinline__ unsigned smem_u32(const void* p) {
    return (unsigned)__cvta_generic_to_shared(p);
}
__device__ __forceinline__ unsigned short f2bf(float v) {
    __nv_bfloat16 h = __float2bfloat16_rn(v);
    return *(unsigned short*)&h;
}
__device__ __forceinline__ unsigned bf2pack(float lo, float hi) {
    __nv_bfloat162 h = __floats2bfloat162_rn(lo, hi);
    return *(unsigned*)&h;
}
__device__ __forceinline__ float2 bfu2f2(unsigned u) {
    float2 r;
    r.x = __uint_as_float(u << 16);
    r.y = __uint_as_float(u & 0xffff0000u);
    return r;
}
__device__ __forceinline__ void ldsm4(unsigned& r0, unsigned& r1, unsigned& r2, unsigned& r3,
                                      unsigned addr) {
    asm volatile("ldmatrix.sync.aligned.m8n8.x4.shared.b16 {%0,%1,%2,%3}, [%4];"
                 : "=r"(r0), "=r"(r1), "=r"(r2), "=r"(r3) : "r"(addr));
}
__device__ __forceinline__ void mma_bf(float* d, const unsigned* a, unsigned b0, unsigned b1) {
    asm volatile(
        "mma.sync.aligned.m16n8k16.row.col.f32.bf16.bf16.f32 "
        "{%0,%1,%2,%3},{%4,%5,%6,%7},{%8,%9},{%0,%1,%2,%3};"
        : "+f"(d[0]), "+f"(d[1]), "+f"(d[2]), "+f"(d[3])
        : "r"(a[0]), "r"(a[1]), "r"(a[2]), "r"(a[3]), "r"(b0), "r"(b1));
}

// ---------------------------------------------------------------------------
// Merged weight transpose+convert for all five GEMM weights.
// ---------------------------------------------------------------------------
#define S_QKV (DIMC*QKVW)
#define S_ACA (DIMC*DIMC)
#define S_WIN (DIMC*DIMC)
#define S_FC1 (DIMC*MLP_HID)
#define S_FC2 (CFF*DIMC)
#define S_TOT (S_QKV+S_ACA+S_WIN+S_FC1+S_FC2)

__global__ void convw_all(const float* __restrict__ qkv_w, const float* __restrict__ aca_w,
                          const float* __restrict__ win_w, const float* __restrict__ fc1_w,
                          const float* __restrict__ fc2_w, unsigned short* __restrict__ wt) {
    int i = blockIdx.x * blockDim.x + threadIdx.x;
    if (i >= S_TOT) return;
    const float* W; int K, N, loc, base;
    if (i < S_QKV)                       { W = qkv_w; K = DIMC; N = QKVW;   loc = i;                         base = WT_QKV; }
    else if (i < S_QKV+S_ACA)            { W = aca_w; K = DIMC; N = DIMC;   loc = i - S_QKV;                 base = WT_ACA; }
    else if (i < S_QKV+S_ACA+S_WIN)      { W = win_w; K = DIMC; N = DIMC;   loc = i - S_QKV - S_ACA;         base = WT_WIN; }
    else if (i < S_QKV+S_ACA+S_WIN+S_FC1){ W = fc1_w; K = DIMC; N = MLP_HID;loc = i - S_QKV - S_ACA - S_WIN; base = WT_FC1; }
    else                                 { W = fc2_w; K = CFF;  N = DIMC;   loc = i - S_QKV-S_ACA-S_WIN-S_FC1; base = WT_FC2; }
    int n = loc / K, k = loc % K;
    wt[base + loc] = f2bf(W[(size_t)k * N + n]);
}

// ---------------------------------------------------------------------------
// Fused dictionary projections: kkn fp32 l2n, vvt bf16 transposed, tdpr fp32
// ---------------------------------------------------------------------------
__global__ void dict_kernel(const float* __restrict__ td,
                            const float* __restrict__ wk_w, const float* __restrict__ wk_b,
                            const float* __restrict__ wv_w, const float* __restrict__ wv_b,
                            const float* __restrict__ ftd_w, const float* __restrict__ ftd_b,
                            float* __restrict__ kkn, unsigned short* __restrict__ vvt,
                            float* __restrict__ tdpr) {
    int r = blockIdx.x;                 // 0..511
    int b = r >> 6, m = r & 63;
    __shared__ float as[DIMC];
    __shared__ float kbuf[RDIM];
    int tid = threadIdx.x;
    const float* ar = td + (size_t)r * DIMC;
    if (tid < DIMC) as[tid] = ar[tid];
    __syncthreads();
    if (tid < DIMC) {
        float acc = wv_b[tid];
        #pragma unroll 4
        for (int k = 0; k < DIMC; k++) acc += as[k] * wv_w[(size_t)k * DIMC + tid];
        vvt[((size_t)b * DIMC + tid) * MTOK + m] = f2bf(acc);
    } else if (tid < DIMC + DTD) {
        int c = tid - DIMC;
        float acc = ftd_b[c];
        #pragma unroll 4
        for (int k = 0; k < DIMC; k++) acc += as[k] * ftd_w[(size_t)k * DTD + c];
        tdpr[(size_t)r * DTD + c] = acc;
    } else if (tid < DIMC + DTD + RDIM) {
        int c = tid - DIMC - DTD;
        float acc = wk_b[c];
        #pragma unroll 4
        for (int k = 0; k < DIMC; k++) acc += as[k] * wk_w[(size_t)k * RDIM + c];
        kbuf[c] = acc;
    }
    __syncthreads();
    if (tid >= DIMC + DTD && tid < DIMC + DTD + RDIM) {
        int c = tid - DIMC - DTD;
        float ss = 0.f;
        #pragma unroll
        for (int j = 0; j < RDIM; j++) ss += kbuf[j] * kbuf[j];
        float inv = 1.f / fmaxf(sqrtf(ss), 1e-12f);
        kkn[(size_t)r * RDIM + c] = kbuf[c] * inv;
    }
}

// ---------------------------------------------------------------------------
// Window attention bias expansion
// ---------------------------------------------------------------------------
__global__ void wbias_kernel(const int* __restrict__ rpi, const float* __restrict__ rpb) {
    int e = blockIdx.x * blockDim.x + threadIdx.x;
    if (e < WINN * WINN) {
        int idx = rpi[e];
        #pragma unroll
        for (int h = 0; h < HEADS; h++) g_wbias[h * WINN * WINN + e] = rpb[idx * HEADS + h];
    }
}

// ---------------------------------------------------------------------------
// LayerNorm -> bf16 out (+ optional fused 10-dim q projection, fp32)
// ---------------------------------------------------------------------------
__global__ void ln_kernel(const float* __restrict__ x, const float* __restrict__ g,
                          const float* __restrict__ b, unsigned short* __restrict__ out,
                          const float* __restrict__ wq, const float* __restrict__ bq,
                          float* __restrict__ qout) {
    __shared__ float ws[1920];
    __shared__ float bqs[16];
    int tid = threadIdx.x;
    if (wq) {
        for (int i = tid; i < 1920; i += 256) ws[i] = (i < DIMC * RDIM) ? wq[i] : 0.f;
        if (tid < RDIM) bqs[tid] = bq[tid];
        __syncthreads();
    }
    int row = (blockIdx.x * blockDim.x + tid) >> 5;
    if (row >= ROWS) return;
    int lane = tid & 31;
    const float* xr = x + (size_t)row * DIMC;
    float v[6], s = 0.f, s2 = 0.f;
    #pragma unroll
    for (int k = 0; k < 6; k++) {
        int c = lane + k * 32;
        v[k] = (c < DIMC) ? xr[c] : 0.f;
        s += v[k]; s2 += v[k] * v[k];
    }
    s = warp_sum(s); s2 = warp_sum(s2);
    float mu = s * (1.f / DIMC);
    float var = s2 * (1.f / DIMC) - mu * mu;
    float rstd = rsqrtf(var + 1e-5f);
    float nv[6];
    unsigned short* orow = out + (size_t)row * DIMC;
    #pragma unroll
    for (int k = 0; k < 6; k++) {
        int c = lane + k * 32;
        nv[k] = (c < DIMC) ? ((v[k] - mu) * rstd * g[c] + b[c]) : 0.f;
        if (c < DIMC) orow[c] = f2bf(nv[k]);
    }
    if (wq) {
        float myq = 0.f;
        #pragma unroll
        for (int o = 0; o < RDIM; o++) {
            float p = 0.f;
            #pragma unroll
            for (int k = 0; k < 6; k++) p += nv[k] * ws[(lane + 32 * k) * RDIM + o];
            p = warp_sum(p);
            if (lane == o) myq = p + bqs[o];
        }
        if (lane < RDIM) qout[(size_t)row * RDIM + lane] = myq;
    }
}

// ---------------------------------------------------------------------------
// bf16 tensor-core GEMM (m16n8k16) with ldmatrix fragment loads.
// Output: fp32 C (full epilogue) or bf16 Cb (bias+act only, paired stores).
// ---------------------------------------------------------------------------
struct GPass { const unsigned short* A; const unsigned short* W; int K; int kt; };

__global__ __launch_bounds__(256) void gemm_bf(
        const unsigned short* __restrict__ A1, const unsigned short* __restrict__ W1, int K1,
        const unsigned short* __restrict__ A2, const unsigned short* __restrict__ W2, int K2,
        const unsigned short* __restrict__ A3, const unsigned short* __restrict__ W3base,
        long w3_stride, int K3,
        const float* __restrict__ b1, const float* __restrict__ b2,
        const float* __restrict__ add1,
        float* __restrict__ C, unsigned short* __restrict__ Cb,
        int M, int N, int ldc, int act) {
    __shared__ unsigned short As[2][128][40];
    __shared__ unsigned short Ws[2][64][40];
    int tid  = threadIdx.x;
    int lane = tid & 31;
    int warp = tid >> 5;
    int warpM = warp & 3;
    int warpN = warp >> 2;
    int gId = lane >> 2;
    int tig = lane & 3;
    int row0 = blockIdx.y * 128;
    int col0 = blockIdx.x * 64;

    GPass ps[3];
    int np = 0;
    if (A1 && K1 > 0) ps[np++] = {A1, W1, K1, (K1 + 31) >> 5};
    if (A2 && K2 > 0) ps[np++] = {A2, W2, K2, (K2 + 31) >> 5};
    if (A3 && K3 > 0) ps[np++] = {A3, W3base + (size_t)(row0 >> 12) * w3_stride, K3, (K3 + 31) >> 5};
    int total = 0;
    for (int p = 0; p < np; p++) total += ps[p].kt;

    auto copy_tile = [&](int gi, int buf) {
        int p = 0, loc = gi;
        while (loc >= ps[p].kt) { loc -= ps[p].kt; p++; }
        const unsigned short* A = ps[p].A;
        const unsigned short* W = ps[p].W;
        int K = ps[p].K;
        int k0 = loc << 5;
        #pragma unroll
        for (int f = 0; f < 4; f++) {
            int c = tid + f * 256;
            int m = c >> 3, kc = (c & 7) << 2;
            int gk = k0 + kc;
            int rem = K - gk;
            int bytes = (rem <= 0) ? 0 : ((rem >= 4) ? 8 : rem * 2);
            const unsigned short* src = bytes ? (A + (size_t)(row0 + m) * K + gk) : A;
            unsigned dst = smem_u32(&As[buf][m][kc]);
            asm volatile("cp.async.ca.shared.global [%0], [%1], 8, %2;"
                         :: "r"(dst), "l"(src), "r"(bytes));
        }
        #pragma unroll
        for (int f = 0; f < 2; f++) {
            int c = tid + f * 256;
            int n = c >> 3, kc = (c & 7) << 2;
            int gn = col0 + n, gk = k0 + kc;
            int bytes = 0;
            if (gn < N) {
                int rem = K - gk;
                bytes = (rem <= 0) ? 0 : ((rem >= 4) ? 8 : rem * 2);
            }
            const unsigned short* src = bytes ? (W + (size_t)gn * K + gk) : W;
            unsigned dst = smem_u32(&Ws[buf][n][kc]);
            asm volatile("cp.async.ca.shared.global [%0], [%1], 8, %2;"
                         :: "r"(dst), "l"(src), "r"(bytes));
        }
    };

    float d[2][4][4];
    #pragma unroll
    for (int mt = 0; mt < 2; mt++)
        #pragma unroll
        for (int nt = 0; nt < 4; nt++)
            #pragma unroll
            for (int i = 0; i < 4; i++) d[mt][nt][i] = 0.f;

    copy_tile(0, 0);
    asm volatile("cp.async.commit_group;");
    for (int i = 0; i < total; i++) {
        asm volatile("cp.async.wait_group 0;");
        __syncthreads();
        if (i + 1 < total) {
            copy_tile(i + 1, (i + 1) & 1);
            asm volatile("cp.async.commit_group;");
        }
        int buf = i & 1;
        #pragma unroll
        for (int ks = 0; ks < 2; ks++) {
            int kb = ks * 16;
            unsigned a[2][4], bfr[4][2];
            int arow = lane & 15;
            int acol = kb + ((lane >> 4) << 3);
            #pragma unroll
            for (int mt = 0; mt < 2; mt++) {
                int m0 = warpM * 32 + mt * 16;
                unsigned ad = smem_u32(&As[buf][m0 + arow][acol]);
                ldsm4(a[mt][0], a[mt][1], a[mt][2], a[mt][3], ad);
            }
            int wrow = ((lane >> 4) << 3) + (lane & 7);
            int wcol = kb + (((lane >> 3) & 1) << 3);
            #pragma unroll
            for (int np2 = 0; np2 < 2; np2++) {
                int n0 = warpN * 32 + np2 * 16;
                unsigned ad = smem_u32(&Ws[buf][n0 + wrow][wcol]);
                unsigned r0, r1, r2, r3;
                ldsm4(r0, r1, r2, r3, ad);
                bfr[2*np2][0] = r0;  bfr[2*np2][1] = r1;
                bfr[2*np2+1][0] = r2; bfr[2*np2+1][1] = r3;
            }
            #pragma unroll
            for (int mt = 0; mt < 2; mt++)
                #pragma unroll
                for (int nt = 0; nt < 4; nt++)
                    mma_bf(d[mt][nt], a[mt], bfr[nt][0], bfr[nt][1]);
        }
    }

    if (Cb) {
        // bf16 output: bias + optional act, paired 4B stores (N even).
        #pragma unroll
        for (int mt = 0; mt < 2; mt++)
            #pragma unroll
            for (int nt = 0; nt < 4; nt++)
                #pragma unroll
                for (int h = 0; h < 2; h++) {
                    int r = row0 + warpM * 32 + mt * 16 + gId + h * 8;
                    int c = col0 + warpN * 32 + nt * 8 + tig * 2;
                    if (c < N) {
                        float v0 = d[mt][nt][2*h], v1 = d[mt][nt][2*h+1];
                        if (b1) { v0 += b1[c]; v1 += b1[c+1]; }
                        if (act) { v0 = gelu_exact(v0); v1 = gelu_exact(v1); }
                        *(unsigned*)&Cb[(size_t)r * ldc + c] = bf2pack(v0, v1);
                    }
                }
    } else {
        #pragma unroll
        for (int mt = 0; mt < 2; mt++) {
            #pragma unroll
            for (int nt = 0; nt < 4; nt++) {
                #pragma unroll
                for (int i = 0; i < 4; i++) {
                    int r = row0 + warpM * 32 + mt * 16 + gId + (i >> 1) * 8;
                    int c = col0 + warpN * 32 + nt * 8 + tig * 2 + (i & 1);
                    if (c < N) {
                        float v = d[mt][nt][i];
                        if (b1)   v += b1[c];
                        if (b2)   v += b2[c];
                        if (add1) v += add1[(size_t)r * N + c];
                        if (act)  v = gelu_exact(v);
                        C[(size_t)r * ldc + c] = v;
                    }
                }
            }
        }
    }
}

// ---------------------------------------------------------------------------
// ATD: softmax probs P (bf16) + argmax tkid. One warp per token. fp32 math.
// ---------------------------------------------------------------------------
__global__ void atd_kernel(const float* __restrict__ qatd, const float* __restrict__ kkn,
                           const float* __restrict__ scale,
                           unsigned short* __restrict__ P, int* __restrict__ tkid) {
    int t = (blockIdx.x * blockDim.x + threadIdx.x) >> 5;
    int lane = threadIdx.x & 31;
    if (t >= ROWS) return;
    int b = t >> 12;
    float q = (lane < RDIM) ? qatd[(size_t)t * RDIM + lane] : 0.f;
    float ss = warp_sum(q * q);
    float qn = q * (1.f / fmaxf(sqrtf(ss), 1e-12f));
    const float* kb = kkn + (size_t)b * MTOK * RDIM;
    float s0 = 0.f, s1 = 0.f;
    #pragma unroll
    for (int d = 0; d < RDIM; d++) {
        float qd = __shfl_sync(0xffffffffu, qn, d);
        s0 += qd * kb[lane * RDIM + d];
        s1 += qd * kb[(lane + 32) * RDIM + d];
    }
    float sc = fminf(fmaxf(scale[0], 0.f), 3.f);
    float ls = 1.f + sc * 4.15888308335967186f;  // log(64)
    s0 *= ls; s1 *= ls;
    float mv = fmaxf(s0, s1);
    int mi = (s0 >= s1) ? lane : lane + 32;
    #pragma unroll
    for (int o = 16; o; o >>= 1) {
        float ov = __shfl_xor_sync(0xffffffffu, mv, o);
        int   oi = __shfl_xor_sync(0xffffffffu, mi, o);
        if (ov > mv || (ov == mv && oi < mi)) { mv = ov; mi = oi; }
    }
    float p0 = __expf(s0 - mv), p1 = __expf(s1 - mv);
    float sum = warp_sum(p0 + p1);
    float inv = 1.f / sum;
    P[(size_t)t * MTOK + lane]      = f2bf(p0 * inv);
    P[(size_t)t * MTOK + lane + 32] = f2bf(p1 * inv);
    if (lane == 0) tkid[t] = mi;
}

// ---------------------------------------------------------------------------
// Single-pass stable counting sort scatter: block = (batch, bin).
// ---------------------------------------------------------------------------
__global__ void sortscatter_kernel(const int* __restrict__ tkid, int* __restrict__ sidx) {
    int b = blockIdx.x >> 6, bin = blockIdx.x & 63;
    const int* tk = tkid + b * NTOK;
    __shared__ int sc[256];
    int t = threadIdx.x;
    int start = t * 16;
    int eq = 0, less = 0;
    int vals[16];
    #pragma unroll
    for (int k = 0; k < 16; k++) {
        vals[k] = tk[start + k];
        eq += (vals[k] == bin);
        less += (vals[k] < bin);
    }
    sc[t] = (less << 16) | eq;
    __syncthreads();
    #pragma unroll
    for (int d = 1; d < 256; d <<= 1) {
        int v = (t >= d) ? sc[t - d] : 0;
        __syncthreads();
        sc[t] += v;
        __syncthreads();
    }
    int base = sc[255] >> 16;
    int pos = base + (sc[t] & 0xffff) - eq;
    #pragma unroll
    for (int k = 0; k < 16; k++)
        if (vals[k] == bin) sidx[b * NTOK + pos++] = start + k;
}

// ---------------------------------------------------------------------------
// Tensor-core AC_MSA grouped attention (flash-style, gathered rows).
// ---------------------------------------------------------------------------
#define APITCH 136

__global__ __launch_bounds__(128) void acmsa_tc(
        const float* __restrict__ qkv, const int* __restrict__ sidx,
        unsigned short* __restrict__ yout) {
    __shared__ unsigned short Qs[GS * 40];
    __shared__ unsigned short Ks[GS * 40];
    __shared__ unsigned short Vt[32 * APITCH];
    int bi = blockIdx.x;
    int hh = bi % HEADS;
    int g  = (bi / HEADS) % NG;
    int b  = bi / (HEADS * NG);
    int lane = threadIdx.x & 31;
    int warp = threadIdx.x >> 5;               // 0..3
    const float scale = 0.18257418583505536f;  // 30^-0.5
    const int* sb = sidx + b * NTOK + g * GS;

    #pragma unroll 4
    for (int u = 0; u < 32; u++) {
        int r = warp * 32 + u;
        int tok = sb[r];
        size_t rb = ((size_t)(b * NTOK + tok)) * QKVW + hh * HD;
        unsigned short qv = 0, kv = 0, vv = 0;
        if (lane < HD) {
            qv = f2bf(qkv[rb + lane] * scale);
            kv = f2bf(qkv[rb + 180 + lane]);
            vv = f2bf(qkv[rb + 360 + lane]);
        }
        Qs[r * 40 + lane] = qv;
        Ks[r * 40 + lane] = kv;
        Vt[lane * APITCH + r] = vv;
    }
    __syncthreads();

    int gId = lane >> 2, tig = lane & 3;
    int m0 = warp * 32;

    unsigned qf[2][2][4];
    #pragma unroll
    for (int mt = 0; mt < 2; mt++)
        #pragma unroll
        for (int ks = 0; ks < 2; ks++) {
            unsigned ad = smem_u32(Qs + (m0 + mt * 16 + (lane & 15)) * 40
                                      + ks * 16 + ((lane >> 4) << 3));
            ldsm4(qf[mt][ks][0], qf[mt][ks][1], qf[mt][ks][2], qf[mt][ks][3], ad);
        }

    float mrow[2][2] = {{-1e30f, -1e30f}, {-1e30f, -1e30f}};
    float lrow[2][2] = {{0.f, 0.f}, {0.f, 0.f}};
    float o[2][4][4];
    #pragma unroll
    for (int mt = 0; mt < 2; mt++)
        #pragma unroll
        for (int vn = 0; vn < 4; vn++)
            #pragma unroll
            for (int i = 0; i < 4; i++) o[mt][vn][i] = 0.f;

    for (int jc = 0; jc < GS; jc += 32) {
        unsigned kf[4][2][2];
        #pragma unroll
        for (int np2 = 0; np2 < 2; np2++)
            #pragma unroll
            for (int ks = 0; ks < 2; ks++) {
                unsigned ad = smem_u32(Ks + (jc + np2 * 16 + ((lane >> 4) << 3) + (lane & 7)) * 40
                                          + ks * 16 + (((lane >> 3) & 1) << 3));
                unsigned r0, r1, r2, r3;
                ldsm4(r0, r1, r2, r3, ad);
                kf[2*np2][ks][0] = r0;   kf[2*np2][ks][1] = r1;
                kf[2*np2+1][ks][0] = r2; kf[2*np2+1][ks][1] = r3;
            }
        float s[2][4][4];
        #pragma unroll
        for (int mt = 0; mt < 2; mt++)
            #pragma unroll
            for (int nt = 0; nt < 4; nt++) {
                #pragma unroll
                for (int i = 0; i < 4; i++) s[mt][nt][i] = 0.f;
                #pragma unroll
                for (int ks = 0; ks < 2; ks++)
                    mma_bf(s[mt][nt], qf[mt][ks], kf[nt][ks][0], kf[nt][ks][1]);
            }
        float co2[2][2];
        #pragma unroll
        for (int mt = 0; mt < 2; mt++)
            #pragma unroll
            for (int h = 0; h < 2; h++) {
                float rm = -1e30f;
                #pragma unroll
                for (int nt = 0; nt < 4; nt++)
                    rm = fmaxf(rm, fmaxf(s[mt][nt][2*h], s[mt][nt][2*h+1]));
                rm = fmaxf(rm, __shfl_xor_sync(0xffffffffu, rm, 1));
                rm = fmaxf(rm, __shfl_xor_sync(0xffffffffu, rm, 2));
                float mn = fmaxf(mrow[mt][h], rm);
                float co = __expf(mrow[mt][h] - mn);
                mrow[mt][h] = mn;
                float rs = 0.f;
                #pragma unroll
                for (int nt = 0; nt < 4; nt++) {
                    float e0 = __expf(s[mt][nt][2*h]   - mn);
                    float e1 = __expf(s[mt][nt][2*h+1] - mn);
                    s[mt][nt][2*h] = e0; s[mt][nt][2*h+1] = e1;
                    rs += e0 + e1;
                }
                rs += __shfl_xor_sync(0xffffffffu, rs, 1);
                rs += __shfl_xor_sync(0xffffffffu, rs, 2);
                lrow[mt][h] = lrow[mt][h] * co + rs;
                co2[mt][h] = co;
            }
        #pragma unroll
        for (int mt = 0; mt < 2; mt++)
            #pragma unroll
            for (int vn = 0; vn < 4; vn++)
                #pragma unroll
                for (int i = 0; i < 4; i++) o[mt][vn][i] *= co2[mt][i >> 1];
        #pragma unroll
        for (int ks = 0; ks < 2; ks++) {
            unsigned a[2][4];
            #pragma unroll
            for (int mt = 0; mt < 2; mt++) {
                a[mt][0] = bf2pack(s[mt][2*ks][0],   s[mt][2*ks][1]);
                a[mt][1] = bf2pack(s[mt][2*ks][2],   s[mt][2*ks][3]);
                a[mt][2] = bf2pack(s[mt][2*ks+1][0], s[mt][2*ks+1][1]);
                a[mt][3] = bf2pack(s[mt][2*ks+1][2], s[mt][2*ks+1][3]);
            }
            #pragma unroll
            for (int vn = 0; vn < 4; vn++) {
                const unsigned short* vp = Vt + (vn * 8 + gId) * APITCH + jc + ks * 16 + 2 * tig;
                unsigned b0 = *(const unsigned*)vp;
                unsigned b1 = *(const unsigned*)(vp + 8);
                #pragma unroll
                for (int mt = 0; mt < 2; mt++)
                    mma_bf(o[mt][vn], a[mt], b0, b1);
            }
        }
    }
    #pragma unroll
    for (int mt = 0; mt < 2; mt++)
        #pragma unroll
        for (int h = 0; h < 2; h++) {
            float inv = 1.f / lrow[mt][h];
            int row = m0 + mt * 16 + gId + 8 * h;
            int tok = sb[row];
            unsigned short* obase = yout + ((size_t)(b * NTOK + tok)) * DIMC + hh * HD;
            #pragma unroll
            for (int vn = 0; vn < 4; vn++) {
                int vd = vn * 8 + 2 * tig;
                if (vd < HD)
                    *(unsigned*)(obase + vd) =
                        bf2pack(o[mt][vn][2*h] * inv, o[mt][vn][2*h+1] * inv);
            }
        }
}

// ---------------------------------------------------------------------------
// Tensor-core window attention (flash-style).
// ---------------------------------------------------------------------------
#define VPITCH 264
#define WSMEM ((2*256*40 + 32*VPITCH) * 2)   // 57856 bytes

__global__ __launch_bounds__(256) void winattn_tc(const float* __restrict__ qkv,
                                                  unsigned short* __restrict__ yout) {
    extern __shared__ unsigned short sm16[];
    unsigned short* Qs = sm16;                 // [256][40]
    unsigned short* Ks = sm16 + 256 * 40;      // [256][40]
    unsigned short* Vt = sm16 + 2 * 256 * 40;  // [32][VPITCH]
    int bi = blockIdx.x;
    int hh = bi % HEADS;
    int wdx = bi / HEADS;
    int b = wdx >> 4;
    int wy = (wdx >> 2) & 3;
    int wx = wdx & 3;
    int lane = threadIdx.x & 31;
    int warp = threadIdx.x >> 5;               // 0..7
    const float scale = 0.18257418583505536f;  // 30^-0.5

    #pragma unroll 4
    for (int u = 0; u < 32; u++) {
        int r = warp * 32 + u;
        int ny = (wy * WS + (r >> 4)) * WW + wx * WS + (r & 15);
        size_t rb = ((size_t)(b * NTOK + ny)) * QKVW + hh * HD;
        unsigned short qv = 0, kv = 0, vv = 0;
        if (lane < HD) {
            qv = f2bf(qkv[rb + lane] * scale);
            kv = f2bf(qkv[rb + 180 + lane]);
            vv = f2bf(qkv[rb + 360 + lane]);
        }
        Qs[r * 40 + lane] = qv;
        Ks[r * 40 + lane] = kv;
        Vt[lane * VPITCH + r] = vv;
    }
    __syncthreads();

    int gId = lane >> 2, tig = lane & 3;
    int m0 = warp * 32;

    unsigned qf[2][2][4];
    #pragma unroll
    for (int mt = 0; mt < 2; mt++)
        #pragma unroll
        for (int ks = 0; ks < 2; ks++) {
            unsigned ad = smem_u32(Qs + (m0 + mt * 16 + (lane & 15)) * 40
                                      + ks * 16 + ((lane >> 4) << 3));
            ldsm4(qf[mt][ks][0], qf[mt][ks][1], qf[mt][ks][2], qf[mt][ks][3], ad);
        }

    float mrow[2][2] = {{-1e30f, -1e30f}, {-1e30f, -1e30f}};
    float lrow[2][2] = {{0.f, 0.f}, {0.f, 0.f}};
    float o[2][4][4];
    #pragma unroll
    for (int mt = 0; mt < 2; mt++)
        #pragma unroll
        for (int vn = 0; vn < 4; vn++)
            #pragma unroll
            for (int i = 0; i < 4; i++) o[mt][vn][i] = 0.f;

    const float* bias = g_wbias + (size_t)hh * WINN * WINN;

    for (int jc = 0; jc < WINN; jc += 32) {
        unsigned kf[4][2][2];
        #pragma unroll
        for (int np2 = 0; np2 < 2; np2++)
            #pragma unroll
            for (int ks = 0; ks < 2; ks++) {
                unsigned ad = smem_u32(Ks + (jc + np2 * 16 + ((lane >> 4) << 3) + (lane & 7)) * 40
                                          + ks * 16 + (((lane >> 3) & 1) << 3));
                unsigned r0, r1, r2, r3;
                ldsm4(r0, r1, r2, r3, ad);
                kf[2*np2][ks][0] = r0;   kf[2*np2][ks][1] = r1;
                kf[2*np2+1][ks][0] = r2; kf[2*np2+1][ks][1] = r3;
            }
        float s[2][4][4];
        #pragma unroll
        for (int mt = 0; mt < 2; mt++)
            #pragma unroll
            for (int nt = 0; nt < 4; nt++) {
                #pragma unroll
                for (int i = 0; i < 4; i++) s[mt][nt][i] = 0.f;
                #pragma unroll
                for (int ks = 0; ks < 2; ks++)
                    mma_bf(s[mt][nt], qf[mt][ks], kf[nt][ks][0], kf[nt][ks][1]);
            }
        #pragma unroll
        for (int mt = 0; mt < 2; mt++)
            #pragma unroll
            for (int h = 0; h < 2; h++) {
                int q = m0 + mt * 16 + gId + 8 * h;
                #pragma unroll
                for (int nt = 0; nt < 4; nt++) {
                    float2 bv = *(const float2*)&bias[(size_t)q * WINN + jc + nt * 8 + 2 * tig];
                    s[mt][nt][2*h]   += bv.x;
                    s[mt][nt][2*h+1] += bv.y;
                }
            }
        float co2[2][2];
        #pragma unroll
        for (int mt = 0; mt < 2; mt++)
            #pragma unroll
            for (int h = 0; h < 2; h++) {
                float rm = -1e30f;
                #pragma unroll
                for (int nt = 0; nt < 4; nt++)
                    rm = fmaxf(rm, fmaxf(s[mt][nt][2*h], s[mt][nt][2*h+1]));
                rm = fmaxf(rm, __shfl_xor_sync(0xffffffffu, rm, 1));
                rm = fmaxf(rm, __shfl_xor_sync(0xffffffffu, rm, 2));
                float mn = fmaxf(mrow[mt][h], rm);
                float co = __expf(mrow[mt][h] - mn);
                mrow[mt][h] = mn;
                float rs = 0.f;
                #pragma unroll
                for (int nt = 0; nt < 4; nt++) {
                    float e0 = __expf(s[mt][nt][2*h]   - mn);
                    float e1 = __expf(s[mt][nt][2*h+1] - mn);
                    s[mt][nt][2*h] = e0; s[mt][nt][2*h+1] = e1;
                    rs += e0 + e1;
                }
                rs += __shfl_xor_sync(0xffffffffu, rs, 1);
                rs += __shfl_xor_sync(0xffffffffu, rs, 2);
                lrow[mt][h] = lrow[mt][h] * co + rs;
                co2[mt][h] = co;
            }
        #pragma unroll
        for (int mt = 0; mt < 2; mt++)
            #pragma unroll
            for (int vn = 0; vn < 4; vn++)
                #pragma unroll
                for (int i = 0; i < 4; i++) o[mt][vn][i] *= co2[mt][i >> 1];
        #pragma unroll
        for (int ks = 0; ks < 2; ks++) {
            unsigned a[2][4];
            #pragma unroll
            for (int mt = 0; mt < 2; mt++) {
                a[mt][0] = bf2pack(s[mt][2*ks][0],   s[mt][2*ks][1]);
                a[mt][1] = bf2pack(s[mt][2*ks][2],   s[mt][2*ks][3]);
                a[mt][2] = bf2pack(s[mt][2*ks+1][0], s[mt][2*ks+1][1]);
                a[mt][3] = bf2pack(s[mt][2*ks+1][2], s[mt][2*ks+1][3]);
            }
            #pragma unroll
            for (int vn = 0; vn < 4; vn++) {
                const unsigned short* vp = Vt + (vn * 8 + gId) * VPITCH + jc + ks * 16 + 2 * tig;
                unsigned b0 = *(const unsigned*)vp;
                unsigned b1 = *(const unsigned*)(vp + 8);
                #pragma unroll
                for (int mt = 0; mt < 2; mt++)
                    mma_bf(o[mt][vn], a[mt], b0, b1);
            }
        }
    }
    #pragma unroll
    for (int mt = 0; mt < 2; mt++)
        #pragma unroll
        for (int h = 0; h < 2; h++) {
            float inv = 1.f / lrow[mt][h];
            int row = m0 + mt * 16 + gId + 8 * h;
            int ny = (wy * WS + (row >> 4)) * WW + wx * WS + (row & 15);
            unsigned short* obase = yout + ((size_t)(b * NTOK + ny)) * DIMC + hh * HD;
            #pragma unroll
            for (int vn = 0; vn < 4; vn++) {
                int vd = vn * 8 + 2 * tig;
                if (vd < HD)
                    *(unsigned*)(obase + vd) =
                        bf2pack(o[mt][vn][2*h] * inv, o[mt][vn][2*h+1] * inv);
            }
        }
}

// ---------------------------------------------------------------------------
// Gather per-token dictionary features into hc[:, 360:424] (bf16)
// ---------------------------------------------------------------------------
__global__ void gathertd_kernel(const float* __restrict__ tdproj, const int* __restrict__ tkid,
                                unsigned short* __restrict__ hc) {
    int e = blockIdx.x * blockDim.x + threadIdx.x;
    if (e < ROWS * DTD) {
        int r = e >> 6, j = e & 63;
        int b = r >> 12;
        hc[(size_t)r * CFF + MLP_HID + j] =
            f2bf(tdproj[((size_t)b * MTOK + tkid[r]) * DTD + j]);
    }
}

// ---------------------------------------------------------------------------
// Depthwise 5x5 conv + GELU + residual; bf16 in (hc) / bf16 out (hc2).
// Halo tile converted to fp32 smem once; inner loop unchanged.
// ---------------------------------------------------------------------------
#define DWCH 8
__global__ void dwconv_kernel(const unsigned short* __restrict__ hc, const float* __restrict__ w,
                              const float* __restrict__ bias, unsigned short* __restrict__ hc2) {
    __shared__ float smd[20 * 20 * DWCH];
    __shared__ float wsm[25][DWCH];
    __shared__ float bsm[DWCH];
    int tid = threadIdx.x;
    int c0 = blockIdx.y * DWCH;
    int b  = blockIdx.z;
    int tileY = (blockIdx.x >> 2) * 16, tileX = (blockIdx.x & 3) * 16;
    if (tid < 200) { int t5 = tid % 25, j = tid / 25; wsm[t5][j] = w[(c0 + j) * 25 + t5]; }
    if (tid < DWCH) bsm[tid] = bias[c0 + tid];
    for (int i = tid; i < 400; i += 256) {
        int cy = i / 20, cx = i % 20;
        int gy = tileY + cy - 2, gx = tileX + cx - 2;
        uint4 v = {0u, 0u, 0u, 0u};
        if (gy >= 0 && gy < 64 && gx >= 0 && gx < 64)
            v = *(const uint4*)&hc[(((size_t)b << 12) + (gy << 6) + gx) * CFF + c0];
        float2 f0 = bfu2f2(v.x), f1 = bfu2f2(v.y), f2 = bfu2f2(v.z), f3 = bfu2f2(v.w);
        float* dst = &smd[i * 8];
        dst[0] = f0.x; dst[1] = f0.y; dst[2] = f1.x; dst[3] = f1.y;
        dst[4] = f2.x; dst[5] = f2.y; dst[6] = f3.x; dst[7] = f3.y;
    }
    __syncthreads();
    int ty = tid >> 4, tx = tid & 15;
    float acc[DWCH];
    #pragma unroll
    for (int j = 0; j < DWCH; j++) acc[j] = 0.f;
    #pragma unroll
    for (int ky = 0; ky < 5; ky++) {
        #pragma unroll
        for (int kx = 0; kx < 5; kx++) {
            const float* cp = &smd[((ty + ky) * 20 + tx + kx) * 8];
            float4 a0 = *(const float4*)cp;
            float4 a1 = *(const float4*)(cp + 4);
            int t5 = ky * 5 + kx;
            acc[0] += a0.x * wsm[t5][0];
            acc[1] += a0.y * wsm[t5][1];
            acc[2] += a0.z * wsm[t5][2];
            acc[3] += a0.w * wsm[t5][3];
            acc[4] += a1.x * wsm[t5][4];
            acc[5] += a1.y * wsm[t5][5];
            acc[6] += a1.z * wsm[t5][6];
            acc[7] += a1.w * wsm[t5][7];
        }
    }
    const float* ctr = &smd[((ty + 2) * 20 + tx + 2) * 8];
    size_t idx = (((size_t)b << 12) + ((size_t)(tileY + ty) << 6) + (tileX + tx)) * CFF + c0;
    float o[8];
    #pragma unroll
    for (int j = 0; j < 8; j++) o[j] = ctr[j] + gelu_exact(acc[j] + bsm[j]);
    uint4 pk;
    pk.x = bf2pack(o[0], o[1]);
    pk.y = bf2pack(o[2], o[3]);
    pk.z = bf2pack(o[4], o[5]);
    pk.w = bf2pack(o[6], o[7]);
    *(uint4*)&hc2[idx] = pk;
}

// ---------------------------------------------------------------------------
// Launch: two-stream DAG with tensor-core winattn + acmsa, bf16 hc pipeline.
// ---------------------------------------------------------------------------
extern "C" void kernel_launch(void* const* d_in, const int* in_sizes, int n_in,
                              void* d_out, int out_size) {
    const float* x        = (const float*)d_in[0];
    const float* td       = (const float*)d_in[1];
    const float* n1g      = (const float*)d_in[2];
    const float* n1b      = (const float*)d_in[3];
    const float* wqkv_w   = (const float*)d_in[4];
    const float* wqkv_b   = (const float*)d_in[5];
    const float* atd_wq_w = (const float*)d_in[6];
    const float* atd_wq_b = (const float*)d_in[7];
    const float* atd_wk_w = (const float*)d_in[8];
    const float* atd_wk_b = (const float*)d_in[9];
    const float* atd_wv_w = (const float*)d_in[10];
    const float* atd_wv_b = (const float*)d_in[11];
    const float* atd_sc   = (const float*)d_in[12];
    const float* aca_w    = (const float*)d_in[13];
    const float* aca_b    = (const float*)d_in[14];
    const float* win_rpb  = (const float*)d_in[15];
    const float* win_w    = (const float*)d_in[16];
    const float* win_b    = (const float*)d_in[17];
    const float* fctd_w   = (const float*)d_in[18];
    const float* fctd_b   = (const float*)d_in[19];
    const float* fc1_w    = (const float*)d_in[20];
    const float* fc1_b    = (const float*)d_in[21];
    const float* dw_w     = (const float*)d_in[22];
    const float* dw_b     = (const float*)d_in[23];
    const float* fc2_w    = (const float*)d_in[24];
    const float* fc2_b    = (const float*)d_in[25];
    const float* n2g      = (const float*)d_in[26];
    const float* n2b      = (const float*)d_in[27];
    const int*   rpi      = (const int*)d_in[28];
    float* out = (float*)d_out;

    float *qkv, *qatd, *kkn, *tdpr, *xsum;
    unsigned short *xn, *x2n, *yaca, *ywin, *patd, *hc, *hc2, *vvt, *wt;
    int *tkid, *sidx;
    cudaGetSymbolAddress((void**)&xn,   g_xn);
    cudaGetSymbolAddress((void**)&qkv,  g_qkv);
    cudaGetSymbolAddress((void**)&qatd, g_qatd);
    cudaGetSymbolAddress((void**)&kkn,  g_kkn);
    cudaGetSymbolAddress((void**)&vvt,  g_vvt);
    cudaGetSymbolAddress((void**)&tdpr, g_tdpr);
    cudaGetSymbolAddress((void**)&patd, g_patd);
    cudaGetSymbolAddress((void**)&yaca, g_yaca);
    cudaGetSymbolAddress((void**)&ywin, g_ywin);
    cudaGetSymbolAddress((void**)&xsum, g_xsum);
    cudaGetSymbolAddress((void**)&x2n,  g_x2n);
    cudaGetSymbolAddress((void**)&hc,   g_hc);
    cudaGetSymbolAddress((void**)&hc2,  g_hc2);
    cudaGetSymbolAddress((void**)&tkid, g_tkid);
    cudaGetSymbolAddress((void**)&sidx, g_sidx);
    cudaGetSymbolAddress((void**)&wt,   g_wt);

    static cudaStream_t s1 = nullptr;
    static cudaEvent_t eRoot, eLn1, eConvw, eWbias, eQkv, eAcmsa, eGath;
    if (!s1) {
        cudaStreamCreateWithFlags(&s1, cudaStreamNonBlocking);
        cudaEventCreateWithFlags(&eRoot,  cudaEventDisableTiming);
        cudaEventCreateWithFlags(&eLn1,   cudaEventDisableTiming);
        cudaEventCreateWithFlags(&eConvw, cudaEventDisableTiming);
        cudaEventCreateWithFlags(&eWbias, cudaEventDisableTiming);
        cudaEventCreateWithFlags(&eQkv,   cudaEventDisableTiming);
        cudaEventCreateWithFlags(&eAcmsa, cudaEventDisableTiming);
        cudaEventCreateWithFlags(&eGath,  cudaEventDisableTiming);
        cudaFuncSetAttribute(winattn_tc, cudaFuncAttributeMaxDynamicSharedMemorySize, WSMEM);
    }

    // ---- fork side stream from main ----
    cudaEventRecord(eRoot, 0);
    cudaStreamWaitEvent(s1, eRoot, 0);

    // ---- side stream: prologue kernels ----
    convw_all<<<(S_TOT + 255)/256, 256, 0, s1>>>(wqkv_w, aca_w, win_w, fc1_w, fc2_w, wt);
    cudaEventRecord(eConvw, s1);
    wbias_kernel<<<WINN*WINN/256, 256, 0, s1>>>(rpi, win_rpb);
    cudaEventRecord(eWbias, s1);
    dict_kernel<<<BATCH*MTOK, 256, 0, s1>>>(td, atd_wk_w, atd_wk_b, atd_wv_w, atd_wv_b,
                                            fctd_w, fctd_b, kkn, vvt, tdpr);

    // ---- main stream: LN1 (+ fused q_atd) ----
    ln_kernel<<<ROWS/8, 256>>>(x, n1g, n1b, xn, atd_wq_w, atd_wq_b, qatd);
    cudaEventRecord(eLn1, 0);

    // main: qkv GEMM (needs convw)
    cudaStreamWaitEvent(0, eConvw, 0);
    gemm_bf<<<dim3(9, ROWS/128), 256>>>(xn, wt + WT_QKV, DIMC, nullptr, nullptr, 0,
                                        nullptr, nullptr, 0, 0,
                                        wqkv_b, nullptr, nullptr,
                                        qkv, nullptr, ROWS, QKVW, QKVW, 0);
    cudaEventRecord(eQkv, 0);

    // main: tensor-core window attention (needs qkv + wbias)
    cudaStreamWaitEvent(0, eWbias, 0);
    winattn_tc<<<NWIN*HEADS, 256, WSMEM>>>(qkv, ywin);

    // ---- side stream: ATD chain (needs ln1; acmsa needs qkv) ----
    cudaStreamWaitEvent(s1, eLn1, 0);
    atd_kernel<<<ROWS/8, 256, 0, s1>>>(qatd, kkn, atd_sc, patd, tkid);
    sortscatter_kernel<<<BATCH*MTOK, 256, 0, s1>>>(tkid, sidx);
    cudaStreamWaitEvent(s1, eQkv, 0);
    acmsa_tc<<<BATCH*NG*HEADS, 128, 0, s1>>>(qkv, sidx, yaca);
    cudaEventRecord(eAcmsa, s1);
    gathertd_kernel<<<ROWS*DTD/256, 256, 0, s1>>>(tdpr, tkid, hc);
    cudaEventRecord(eGath, s1);

    // ---- main stream: join acmsa branch, fused residual GEMM ----
    cudaStreamWaitEvent(0, eAcmsa, 0);
    gemm_bf<<<dim3(3, ROWS/128), 256>>>(yaca, wt + WT_ACA, DIMC, ywin, wt + WT_WIN, DIMC,
                                        patd, vvt, (long)DIMC*MTOK, MTOK,
                                        aca_b, win_b, x,
                                        xsum, nullptr, ROWS, DIMC, DIMC, 0);
    ln_kernel<<<ROWS/8, 256>>>(xsum, n2g, n2b, x2n, nullptr, nullptr, nullptr);
    // fc1 + GELU -> hc[:, 0:360] in bf16
    gemm_bf<<<dim3(6, ROWS/128), 256>>>(x2n, wt + WT_FC1, DIMC, nullptr, nullptr, 0,
                                        nullptr, nullptr, 0, 0,
                                        fc1_b, nullptr, nullptr,
                                        nullptr, hc, ROWS, MLP_HID, CFF, 1);
    cudaStreamWaitEvent(0, eGath, 0);
    dwconv_kernel<<<dim3(16, CFF/DWCH, BATCH), 256>>>(hc, dw_w, dw_b, hc2);
    gemm_bf<<<dim3(3, ROWS/128), 256>>>(hc2, wt + WT_FC2, CFF, nullptr, nullptr, 0,
                                        nullptr, nullptr, 0, 0,
                                        fc2_b, nullptr, xsum,
                                        out, nullptr, ROWS, DIMC, DIMC, 0);
}

// round 16
// speedup vs baseline: 1.0124x; 1.0124x over previous
#include <cuda_runtime.h>
#include <cuda_bf16.h>
#include <math.h>

// ---------------------------------------------------------------------------
// Problem constants
// ---------------------------------------------------------------------------
#define BATCH 8
#define NTOK 4096
#define ROWS (BATCH*NTOK)
#define DIMC 180
#define HEADS 6
#define HD 30
#define QKVW 540
#define MTOK 64
#define RDIM 10
#define GS 128
#define NG 32
#define WS 16
#define WINN 256
#define NWIN 128
#define MLP_HID 360
#define DTD 64
#define CFF 424
#define HH 64
#define WW 64

// bf16 weight scratch offsets (elements)
#define WT_QKV 0
#define WT_ACA (WT_QKV + DIMC*QKVW)
#define WT_WIN (WT_ACA + DIMC*DIMC)
#define WT_FC1 (WT_WIN + DIMC*DIMC)
#define WT_FC2 (WT_FC1 + DIMC*MLP_HID)
#define WT_TOTAL (WT_FC2 + CFF*DIMC)

// ---------------------------------------------------------------------------
// Scratch
// ---------------------------------------------------------------------------
__device__ unsigned short g_xn  [ROWS*DIMC];        // bf16
__device__ float g_qkv  [ROWS*QKVW];
__device__ float g_qatd [ROWS*RDIM];
__device__ float g_kkn  [BATCH*MTOK*RDIM];
__device__ unsigned short g_vvt [BATCH*DIMC*MTOK];  // bf16, transposed [b][n][m]
__device__ float g_tdpr [BATCH*MTOK*DTD];
__device__ unsigned short g_patd[ROWS*MTOK];        // bf16
__device__ int   g_tkid [ROWS];
__device__ int   g_sidx [ROWS];
__device__ unsigned short g_yaca[ROWS*DIMC];        // bf16
__device__ unsigned short g_ywin[ROWS*DIMC];        // bf16
__device__ float g_xsum [ROWS*DIMC];
__device__ unsigned short g_x2n [ROWS*DIMC];        // bf16
__device__ float g_hc   [ROWS*CFF];                 // fp32 (R15 bf16 reverted)
__device__ unsigned short g_hc2 [ROWS*CFF];         // bf16
__device__ float g_wbias[HEADS*WINN*WINN];
__device__ unsigned short g_wt  [WT_TOTAL];         // bf16 transposed weights

// ---------------------------------------------------------------------------
// Helpers
// ---------------------------------------------------------------------------
__device__ __forceinline__ float warp_sum(float v) {
    #pragma unroll
    for (int o = 16; o; o >>= 1) v += __shfl_xor_sync(0xffffffffu, v, o);
    return v;
}
__device__ __forceinline__ float gelu_exact(float v) {
    return 0.5f * v * (1.0f + erff(v * 0.70710678118654752440f));
}
__device__ __forceinline__ unsigned smem_u32(const void* p) {
    return (unsigned)__cvta_generic_to_shared(p);
}
__device__ __forceinline__ unsigned short f2bf(float v) {
    __nv_bfloat16 h = __float2bfloat16_rn(v);
    return *(unsigned short*)&h;
}
__device__ __forceinline__ unsigned bf2pack(float lo, float hi) {
    __nv_bfloat162 h = __floats2bfloat162_rn(lo, hi);
    return *(unsigned*)&h;
}
__device__ __forceinline__ void ldsm4(unsigned& r0, unsigned& r1, unsigned& r2, unsigned& r3,
                                      unsigned addr) {
    asm volatile("ldmatrix.sync.aligned.m8n8.x4.shared.b16 {%0,%1,%2,%3}, [%4];"
                 : "=r"(r0), "=r"(r1), "=r"(r2), "=r"(r3) : "r"(addr));
}
__device__ __forceinline__ void mma_bf(float* d, const unsigned* a, unsigned b0, unsigned b1) {
    asm volatile(
        "mma.sync.aligned.m16n8k16.row.col.f32.bf16.bf16.f32 "
        "{%0,%1,%2,%3},{%4,%5,%6,%7},{%8,%9},{%0,%1,%2,%3};"
        : "+f"(d[0]), "+f"(d[1]), "+f"(d[2]), "+f"(d[3])
        : "r"(a[0]), "r"(a[1]), "r"(a[2]), "r"(a[3]), "r"(b0), "r"(b1));
}

// ---------------------------------------------------------------------------
// Merged weight transpose+convert for all five GEMM weights.
// ---------------------------------------------------------------------------
#define S_QKV (DIMC*QKVW)
#define S_ACA (DIMC*DIMC)
#define S_WIN (DIMC*DIMC)
#define S_FC1 (DIMC*MLP_HID)
#define S_FC2 (CFF*DIMC)
#define S_TOT (S_QKV+S_ACA+S_WIN+S_FC1+S_FC2)

__global__ void convw_all(const float* __restrict__ qkv_w, const float* __restrict__ aca_w,
                          const float* __restrict__ win_w, const float* __restrict__ fc1_w,
                          const float* __restrict__ fc2_w, unsigned short* __restrict__ wt) {
    int i = blockIdx.x * blockDim.x + threadIdx.x;
    if (i >= S_TOT) return;
    const float* W; int K, N, loc, base;
    if (i < S_QKV)                       { W = qkv_w; K = DIMC; N = QKVW;   loc = i;                         base = WT_QKV; }
    else if (i < S_QKV+S_ACA)            { W = aca_w; K = DIMC; N = DIMC;   loc = i - S_QKV;                 base = WT_ACA; }
    else if (i < S_QKV+S_ACA+S_WIN)      { W = win_w; K = DIMC; N = DIMC;   loc = i - S_QKV - S_ACA;         base = WT_WIN; }
    else if (i < S_QKV+S_ACA+S_WIN+S_FC1){ W = fc1_w; K = DIMC; N = MLP_HID;loc = i - S_QKV - S_ACA - S_WIN; base = WT_FC1; }
    else                                 { W = fc2_w; K = CFF;  N = DIMC;   loc = i - S_QKV-S_ACA-S_WIN-S_FC1; base = WT_FC2; }
    int n = loc / K, k = loc % K;
    wt[base + loc] = f2bf(W[(size_t)k * N + n]);
}

// ---------------------------------------------------------------------------
// Fused dictionary projections: kkn fp32 l2n, vvt bf16 transposed, tdpr fp32
// ---------------------------------------------------------------------------
__global__ void dict_kernel(const float* __restrict__ td,
                            const float* __restrict__ wk_w, const float* __restrict__ wk_b,
                            const float* __restrict__ wv_w, const float* __restrict__ wv_b,
                            const float* __restrict__ ftd_w, const float* __restrict__ ftd_b,
                            float* __restrict__ kkn, unsigned short* __restrict__ vvt,
                            float* __restrict__ tdpr) {
    int r = blockIdx.x;                 // 0..511
    int b = r >> 6, m = r & 63;
    __shared__ float as[DIMC];
    __shared__ float kbuf[RDIM];
    int tid = threadIdx.x;
    const float* ar = td + (size_t)r * DIMC;
    if (tid < DIMC) as[tid] = ar[tid];
    __syncthreads();
    if (tid < DIMC) {
        float acc = wv_b[tid];
        #pragma unroll 4
        for (int k = 0; k < DIMC; k++) acc += as[k] * wv_w[(size_t)k * DIMC + tid];
        vvt[((size_t)b * DIMC + tid) * MTOK + m] = f2bf(acc);
    } else if (tid < DIMC + DTD) {
        int c = tid - DIMC;
        float acc = ftd_b[c];
        #pragma unroll 4
        for (int k = 0; k < DIMC; k++) acc += as[k] * ftd_w[(size_t)k * DTD + c];
        tdpr[(size_t)r * DTD + c] = acc;
    } else if (tid < DIMC + DTD + RDIM) {
        int c = tid - DIMC - DTD;
        float acc = wk_b[c];
        #pragma unroll 4
        for (int k = 0; k < DIMC; k++) acc += as[k] * wk_w[(size_t)k * RDIM + c];
        kbuf[c] = acc;
    }
    __syncthreads();
    if (tid >= DIMC + DTD && tid < DIMC + DTD + RDIM) {
        int c = tid - DIMC - DTD;
        float ss = 0.f;
        #pragma unroll
        for (int j = 0; j < RDIM; j++) ss += kbuf[j] * kbuf[j];
        float inv = 1.f / fmaxf(sqrtf(ss), 1e-12f);
        kkn[(size_t)r * RDIM + c] = kbuf[c] * inv;
    }
}

// ---------------------------------------------------------------------------
// Window attention bias expansion
// ---------------------------------------------------------------------------
__global__ void wbias_kernel(const int* __restrict__ rpi, const float* __restrict__ rpb) {
    int e = blockIdx.x * blockDim.x + threadIdx.x;
    if (e < WINN * WINN) {
        int idx = rpi[e];
        #pragma unroll
        for (int h = 0; h < HEADS; h++) g_wbias[h * WINN * WINN + e] = rpb[idx * HEADS + h];
    }
}

// ---------------------------------------------------------------------------
// LayerNorm -> bf16 out (+ optional fused 10-dim q projection, fp32).
// Vectorized float2 path: 3 ld.64 + 3 st.32-pair per lane (was 6 + 6 scalar).
// ---------------------------------------------------------------------------
__global__ void ln_kernel(const float* __restrict__ x, const float* __restrict__ g,
                          const float* __restrict__ b, unsigned short* __restrict__ out,
                          const float* __restrict__ wq, const float* __restrict__ bq,
                          float* __restrict__ qout) {
    __shared__ float ws[1920];
    __shared__ float bqs[16];
    int tid = threadIdx.x;
    if (wq) {
        for (int i = tid; i < 1920; i += 256) ws[i] = (i < DIMC * RDIM) ? wq[i] : 0.f;
        if (tid < RDIM) bqs[tid] = bq[tid];
        __syncthreads();
    }
    int row = (blockIdx.x * blockDim.x + tid) >> 5;
    if (row >= ROWS) return;
    int lane = tid & 31;
    const float2* xr = (const float2*)(x + (size_t)row * DIMC);   // 90 float2
    float2 v[3];
    float s = 0.f, s2 = 0.f;
    #pragma unroll
    for (int k = 0; k < 3; k++) {
        int idx = lane + k * 32;
        v[k] = (idx < 90) ? xr[idx] : make_float2(0.f, 0.f);
        s += v[k].x + v[k].y;
        s2 += v[k].x * v[k].x + v[k].y * v[k].y;
    }
    s = warp_sum(s); s2 = warp_sum(s2);
    float mu = s * (1.f / DIMC);
    float var = s2 * (1.f / DIMC) - mu * mu;
    float rstd = rsqrtf(var + 1e-5f);
    float2 nv[3];
    unsigned* orow = (unsigned*)(out + (size_t)row * DIMC);
    const float2* g2 = (const float2*)g;
    const float2* b2 = (const float2*)b;
    #pragma unroll
    for (int k = 0; k < 3; k++) {
        int idx = lane + k * 32;
        if (idx < 90) {
            float2 gg = g2[idx], bb = b2[idx];
            nv[k].x = (v[k].x - mu) * rstd * gg.x + bb.x;
            nv[k].y = (v[k].y - mu) * rstd * gg.y + bb.y;
            orow[idx] = bf2pack(nv[k].x, nv[k].y);
        } else {
            nv[k] = make_float2(0.f, 0.f);
        }
    }
    if (wq) {
        float myq = 0.f;
        #pragma unroll
        for (int o = 0; o < RDIM; o++) {
            float p = 0.f;
            #pragma unroll
            for (int k = 0; k < 3; k++) {
                int idx = lane + k * 32;           // max 95 -> ws idx max 1919, in bounds
                p += nv[k].x * ws[(2 * idx) * RDIM + o]
                   + nv[k].y * ws[(2 * idx + 1) * RDIM + o];
            }
            p = warp_sum(p);
            if (lane == o) myq = p + bqs[o];
        }
        if (lane < RDIM) qout[(size_t)row * RDIM + lane] = myq;
    }
}

// ---------------------------------------------------------------------------
// bf16 tensor-core GEMM (m16n8k16) with ldmatrix fragment loads.
// ---------------------------------------------------------------------------
struct GPass { const unsigned short* A; const unsigned short* W; int K; int kt; };

__global__ __launch_bounds__(256) void gemm_bf(
        const unsigned short* __restrict__ A1, const unsigned short* __restrict__ W1, int K1,
        const unsigned short* __restrict__ A2, const unsigned short* __restrict__ W2, int K2,
        const unsigned short* __restrict__ A3, const unsigned short* __restrict__ W3base,
        long w3_stride, int K3,
        const float* __restrict__ b1, const float* __restrict__ b2,
        const float* __restrict__ add1,
        float* __restrict__ C, int M, int N, int ldc, int act) {
    __shared__ unsigned short As[2][128][40];
    __shared__ unsigned short Ws[2][64][40];
    int tid  = threadIdx.x;
    int lane = tid & 31;
    int warp = tid >> 5;
    int warpM = warp & 3;
    int warpN = warp >> 2;
    int gId = lane >> 2;
    int tig = lane & 3;
    int row0 = blockIdx.y * 128;
    int col0 = blockIdx.x * 64;

    GPass ps[3];
    int np = 0;
    if (A1 && K1 > 0) ps[np++] = {A1, W1, K1, (K1 + 31) >> 5};
    if (A2 && K2 > 0) ps[np++] = {A2, W2, K2, (K2 + 31) >> 5};
    if (A3 && K3 > 0) ps[np++] = {A3, W3base + (size_t)(row0 >> 12) * w3_stride, K3, (K3 + 31) >> 5};
    int total = 0;
    for (int p = 0; p < np; p++) total += ps[p].kt;

    auto copy_tile = [&](int gi, int buf) {
        int p = 0, loc = gi;
        while (loc >= ps[p].kt) { loc -= ps[p].kt; p++; }
        const unsigned short* A = ps[p].A;
        const unsigned short* W = ps[p].W;
        int K = ps[p].K;
        int k0 = loc << 5;
        #pragma unroll
        for (int f = 0; f < 4; f++) {
            int c = tid + f * 256;
            int m = c >> 3, kc = (c & 7) << 2;
            int gk = k0 + kc;
            int rem = K - gk;
            int bytes = (rem <= 0) ? 0 : ((rem >= 4) ? 8 : rem * 2);
            const unsigned short* src = bytes ? (A + (size_t)(row0 + m) * K + gk) : A;
            unsigned dst = smem_u32(&As[buf][m][kc]);
            asm volatile("cp.async.ca.shared.global [%0], [%1], 8, %2;"
                         :: "r"(dst), "l"(src), "r"(bytes));
        }
        #pragma unroll
        for (int f = 0; f < 2; f++) {
            int c = tid + f * 256;
            int n = c >> 3, kc = (c & 7) << 2;
            int gn = col0 + n, gk = k0 + kc;
            int bytes = 0;
            if (gn < N) {
                int rem = K - gk;
                bytes = (rem <= 0) ? 0 : ((rem >= 4) ? 8 : rem * 2);
            }
            const unsigned short* src = bytes ? (W + (size_t)gn * K + gk) : W;
            unsigned dst = smem_u32(&Ws[buf][n][kc]);
            asm volatile("cp.async.ca.shared.global [%0], [%1], 8, %2;"
                         :: "r"(dst), "l"(src), "r"(bytes));
        }
    };

    float d[2][4][4];
    #pragma unroll
    for (int mt = 0; mt < 2; mt++)
        #pragma unroll
        for (int nt = 0; nt < 4; nt++)
            #pragma unroll
            for (int i = 0; i < 4; i++) d[mt][nt][i] = 0.f;

    copy_tile(0, 0);
    asm volatile("cp.async.commit_group;");
    for (int i = 0; i < total; i++) {
        asm volatile("cp.async.wait_group 0;");
        __syncthreads();
        if (i + 1 < total) {
            copy_tile(i + 1, (i + 1) & 1);
            asm volatile("cp.async.commit_group;");
        }
        int buf = i & 1;
        #pragma unroll
        for (int ks = 0; ks < 2; ks++) {
            int kb = ks * 16;
            unsigned a[2][4], bfr[4][2];
            int arow = lane & 15;
            int acol = kb + ((lane >> 4) << 3);
            #pragma unroll
            for (int mt = 0; mt < 2; mt++) {
                int m0 = warpM * 32 + mt * 16;
                unsigned ad = smem_u32(&As[buf][m0 + arow][acol]);
                ldsm4(a[mt][0], a[mt][1], a[mt][2], a[mt][3], ad);
            }
            int wrow = ((lane >> 4) << 3) + (lane & 7);
            int wcol = kb + (((lane >> 3) & 1) << 3);
            #pragma unroll
            for (int np2 = 0; np2 < 2; np2++) {
                int n0 = warpN * 32 + np2 * 16;
                unsigned ad = smem_u32(&Ws[buf][n0 + wrow][wcol]);
                unsigned r0, r1, r2, r3;
                ldsm4(r0, r1, r2, r3, ad);
                bfr[2*np2][0] = r0;  bfr[2*np2][1] = r1;
                bfr[2*np2+1][0] = r2; bfr[2*np2+1][1] = r3;
            }
            #pragma unroll
            for (int mt = 0; mt < 2; mt++)
                #pragma unroll
                for (int nt = 0; nt < 4; nt++)
                    mma_bf(d[mt][nt], a[mt], bfr[nt][0], bfr[nt][1]);
        }
    }

    #pragma unroll
    for (int mt = 0; mt < 2; mt++) {
        #pragma unroll
        for (int nt = 0; nt < 4; nt++) {
            #pragma unroll
            for (int i = 0; i < 4; i++) {
                int r = row0 + warpM * 32 + mt * 16 + gId + (i >> 1) * 8;
                int c = col0 + warpN * 32 + nt * 8 + tig * 2 + (i & 1);
                if (c < N) {
                    float v = d[mt][nt][i];
                    if (b1)   v += b1[c];
                    if (b2)   v += b2[c];
                    if (add1) v += add1[(size_t)r * N + c];
                    if (act)  v = gelu_exact(v);
                    C[(size_t)r * ldc + c] = v;
                }
            }
        }
    }
}

// ---------------------------------------------------------------------------
// ATD: softmax probs P (bf16) + argmax tkid. One warp per token. fp32 math.
// ---------------------------------------------------------------------------
__global__ void atd_kernel(const float* __restrict__ qatd, const float* __restrict__ kkn,
                           const float* __restrict__ scale,
                           unsigned short* __restrict__ P, int* __restrict__ tkid) {
    int t = (blockIdx.x * blockDim.x + threadIdx.x) >> 5;
    int lane = threadIdx.x & 31;
    if (t >= ROWS) return;
    int b = t >> 12;
    float q = (lane < RDIM) ? qatd[(size_t)t * RDIM + lane] : 0.f;
    float ss = warp_sum(q * q);
    float qn = q * (1.f / fmaxf(sqrtf(ss), 1e-12f));
    const float* kb = kkn + (size_t)b * MTOK * RDIM;
    float s0 = 0.f, s1 = 0.f;
    #pragma unroll
    for (int d = 0; d < RDIM; d++) {
        float qd = __shfl_sync(0xffffffffu, qn, d);
        s0 += qd * kb[lane * RDIM + d];
        s1 += qd * kb[(lane + 32) * RDIM + d];
    }
    float sc = fminf(fmaxf(scale[0], 0.f), 3.f);
    float ls = 1.f + sc * 4.15888308335967186f;  // log(64)
    s0 *= ls; s1 *= ls;
    float mv = fmaxf(s0, s1);
    int mi = (s0 >= s1) ? lane : lane + 32;
    #pragma unroll
    for (int o = 16; o; o >>= 1) {
        float ov = __shfl_xor_sync(0xffffffffu, mv, o);
        int   oi = __shfl_xor_sync(0xffffffffu, mi, o);
        if (ov > mv || (ov == mv && oi < mi)) { mv = ov; mi = oi; }
    }
    float p0 = __expf(s0 - mv), p1 = __expf(s1 - mv);
    float sum = warp_sum(p0 + p1);
    float inv = 1.f / sum;
    P[(size_t)t * MTOK + lane]      = f2bf(p0 * inv);
    P[(size_t)t * MTOK + lane + 32] = f2bf(p1 * inv);
    if (lane == 0) tkid[t] = mi;
}

// ---------------------------------------------------------------------------
// Single-pass stable counting sort scatter: block = (batch, bin).
// ---------------------------------------------------------------------------
__global__ void sortscatter_kernel(const int* __restrict__ tkid, int* __restrict__ sidx) {
    int b = blockIdx.x >> 6, bin = blockIdx.x & 63;
    const int* tk = tkid + b * NTOK;
    __shared__ int sc[256];
    int t = threadIdx.x;
    int start = t * 16;
    int eq = 0, less = 0;
    int vals[16];
    #pragma unroll
    for (int k = 0; k < 16; k++) {
        vals[k] = tk[start + k];
        eq += (vals[k] == bin);
        less += (vals[k] < bin);
    }
    sc[t] = (less << 16) | eq;
    __syncthreads();
    #pragma unroll
    for (int d = 1; d < 256; d <<= 1) {
        int v = (t >= d) ? sc[t - d] : 0;
        __syncthreads();
        sc[t] += v;
        __syncthreads();
    }
    int base = sc[255] >> 16;
    int pos = base + (sc[t] & 0xffff) - eq;
    #pragma unroll
    for (int k = 0; k < 16; k++)
        if (vals[k] == bin) sidx[b * NTOK + pos++] = start + k;
}

// ---------------------------------------------------------------------------
// Tensor-core AC_MSA grouped attention (flash-style, gathered rows).
// ---------------------------------------------------------------------------
#define APITCH 136

__global__ __launch_bounds__(128) void acmsa_tc(
        const float* __restrict__ qkv, const int* __restrict__ sidx,
        unsigned short* __restrict__ yout) {
    __shared__ unsigned short Qs[GS * 40];
    __shared__ unsigned short Ks[GS * 40];
    __shared__ unsigned short Vt[32 * APITCH];
    int bi = blockIdx.x;
    int hh = bi % HEADS;
    int g  = (bi / HEADS) % NG;
    int b  = bi / (HEADS * NG);
    int lane = threadIdx.x & 31;
    int warp = threadIdx.x >> 5;               // 0..3
    const float scale = 0.18257418583505536f;  // 30^-0.5
    const int* sb = sidx + b * NTOK + g * GS;

    #pragma unroll 4
    for (int u = 0; u < 32; u++) {
        int r = warp * 32 + u;
        int tok = sb[r];
        size_t rb = ((size_t)(b * NTOK + tok)) * QKVW + hh * HD;
        unsigned short qv = 0, kv = 0, vv = 0;
        if (lane < HD) {
            qv = f2bf(qkv[rb + lane] * scale);
            kv = f2bf(qkv[rb + 180 + lane]);
            vv = f2bf(qkv[rb + 360 + lane]);
        }
        Qs[r * 40 + lane] = qv;
        Ks[r * 40 + lane] = kv;
        Vt[lane * APITCH + r] = vv;
    }
    __syncthreads();

    int gId = lane >> 2, tig = lane & 3;
    int m0 = warp * 32;

    unsigned qf[2][2][4];
    #pragma unroll
    for (int mt = 0; mt < 2; mt++)
        #pragma unroll
        for (int ks = 0; ks < 2; ks++) {
            unsigned ad = smem_u32(Qs + (m0 + mt * 16 + (lane & 15)) * 40
                                      + ks * 16 + ((lane >> 4) << 3));
            ldsm4(qf[mt][ks][0], qf[mt][ks][1], qf[mt][ks][2], qf[mt][ks][3], ad);
        }

    float mrow[2][2] = {{-1e30f, -1e30f}, {-1e30f, -1e30f}};
    float lrow[2][2] = {{0.f, 0.f}, {0.f, 0.f}};
    float o[2][4][4];
    #pragma unroll
    for (int mt = 0; mt < 2; mt++)
        #pragma unroll
        for (int vn = 0; vn < 4; vn++)
            #pragma unroll
            for (int i = 0; i < 4; i++) o[mt][vn][i] = 0.f;

    for (int jc = 0; jc < GS; jc += 32) {
        unsigned kf[4][2][2];
        #pragma unroll
        for (int np2 = 0; np2 < 2; np2++)
            #pragma unroll
            for (int ks = 0; ks < 2; ks++) {
                unsigned ad = smem_u32(Ks + (jc + np2 * 16 + ((lane >> 4) << 3) + (lane & 7)) * 40
                                          + ks * 16 + (((lane >> 3) & 1) << 3));
                unsigned r0, r1, r2, r3;
                ldsm4(r0, r1, r2, r3, ad);
                kf[2*np2][ks][0] = r0;   kf[2*np2][ks][1] = r1;
                kf[2*np2+1][ks][0] = r2; kf[2*np2+1][ks][1] = r3;
            }
        float s[2][4][4];
        #pragma unroll
        for (int mt = 0; mt < 2; mt++)
            #pragma unroll
            for (int nt = 0; nt < 4; nt++) {
                #pragma unroll
                for (int i = 0; i < 4; i++) s[mt][nt][i] = 0.f;
                #pragma unroll
                for (int ks = 0; ks < 2; ks++)
                    mma_bf(s[mt][nt], qf[mt][ks], kf[nt][ks][0], kf[nt][ks][1]);
            }
        float co2[2][2];
        #pragma unroll
        for (int mt = 0; mt < 2; mt++)
            #pragma unroll
            for (int h = 0; h < 2; h++) {
                float rm = -1e30f;
                #pragma unroll
                for (int nt = 0; nt < 4; nt++)
                    rm = fmaxf(rm, fmaxf(s[mt][nt][2*h], s[mt][nt][2*h+1]));
                rm = fmaxf(rm, __shfl_xor_sync(0xffffffffu, rm, 1));
                rm = fmaxf(rm, __shfl_xor_sync(0xffffffffu, rm, 2));
                float mn = fmaxf(mrow[mt][h], rm);
                float co = __expf(mrow[mt][h] - mn);
                mrow[mt][h] = mn;
                float rs = 0.f;
                #pragma unroll
                for (int nt = 0; nt < 4; nt++) {
                    float e0 = __expf(s[mt][nt][2*h]   - mn);
                    float e1 = __expf(s[mt][nt][2*h+1] - mn);
                    s[mt][nt][2*h] = e0; s[mt][nt][2*h+1] = e1;
                    rs += e0 + e1;
                }
                rs += __shfl_xor_sync(0xffffffffu, rs, 1);
                rs += __shfl_xor_sync(0xffffffffu, rs, 2);
                lrow[mt][h] = lrow[mt][h] * co + rs;
                co2[mt][h] = co;
            }
        #pragma unroll
        for (int mt = 0; mt < 2; mt++)
            #pragma unroll
            for (int vn = 0; vn < 4; vn++)
                #pragma unroll
                for (int i = 0; i < 4; i++) o[mt][vn][i] *= co2[mt][i >> 1];
        #pragma unroll
        for (int ks = 0; ks < 2; ks++) {
            unsigned a[2][4];
            #pragma unroll
            for (int mt = 0; mt < 2; mt++) {
                a[mt][0] = bf2pack(s[mt][2*ks][0],   s[mt][2*ks][1]);
                a[mt][1] = bf2pack(s[mt][2*ks][2],   s[mt][2*ks][3]);
                a[mt][2] = bf2pack(s[mt][2*ks+1][0], s[mt][2*ks+1][1]);
                a[mt][3] = bf2pack(s[mt][2*ks+1][2], s[mt][2*ks+1][3]);
            }
            #pragma unroll
            for (int vn = 0; vn < 4; vn++) {
                const unsigned short* vp = Vt + (vn * 8 + gId) * APITCH + jc + ks * 16 + 2 * tig;
                unsigned b0 = *(const unsigned*)vp;
                unsigned b1 = *(const unsigned*)(vp + 8);
                #pragma unroll
                for (int mt = 0; mt < 2; mt++)
                    mma_bf(o[mt][vn], a[mt], b0, b1);
            }
        }
    }
    #pragma unroll
    for (int mt = 0; mt < 2; mt++)
        #pragma unroll
        for (int h = 0; h < 2; h++) {
            float inv = 1.f / lrow[mt][h];
            int row = m0 + mt * 16 + gId + 8 * h;
            int tok = sb[row];
            unsigned short* obase = yout + ((size_t)(b * NTOK + tok)) * DIMC + hh * HD;
            #pragma unroll
            for (int vn = 0; vn < 4; vn++) {
                int vd = vn * 8 + 2 * tig;
                if (vd < HD)
                    *(unsigned*)(obase + vd) =
                        bf2pack(o[mt][vn][2*h] * inv, o[mt][vn][2*h+1] * inv);
            }
        }
}

// ---------------------------------------------------------------------------
// Tensor-core window attention (flash-style).
// ---------------------------------------------------------------------------
#define VPITCH 264
#define WSMEM ((2*256*40 + 32*VPITCH) * 2)   // 57856 bytes

__global__ __launch_bounds__(256) void winattn_tc(const float* __restrict__ qkv,
                                                  unsigned short* __restrict__ yout) {
    extern __shared__ unsigned short sm16[];
    unsigned short* Qs = sm16;                 // [256][40]
    unsigned short* Ks = sm16 + 256 * 40;      // [256][40]
    unsigned short* Vt = sm16 + 2 * 256 * 40;  // [32][VPITCH]
    int bi = blockIdx.x;
    int hh = bi % HEADS;
    int wdx = bi / HEADS;
    int b = wdx >> 4;
    int wy = (wdx >> 2) & 3;
    int wx = wdx & 3;
    int lane = threadIdx.x & 31;
    int warp = threadIdx.x >> 5;               // 0..7
    const float scale = 0.18257418583505536f;  // 30^-0.5

    #pragma unroll 4
    for (int u = 0; u < 32; u++) {
        int r = warp * 32 + u;
        int ny = (wy * WS + (r >> 4)) * WW + wx * WS + (r & 15);
        size_t rb = ((size_t)(b * NTOK + ny)) * QKVW + hh * HD;
        unsigned short qv = 0, kv = 0, vv = 0;
        if (lane < HD) {
            qv = f2bf(qkv[rb + lane] * scale);
            kv = f2bf(qkv[rb + 180 + lane]);
            vv = f2bf(qkv[rb + 360 + lane]);
        }
        Qs[r * 40 + lane] = qv;
        Ks[r * 40 + lane] = kv;
        Vt[lane * VPITCH + r] = vv;
    }
    __syncthreads();

    int gId = lane >> 2, tig = lane & 3;
    int m0 = warp * 32;

    unsigned qf[2][2][4];
    #pragma unroll
    for (int mt = 0; mt < 2; mt++)
        #pragma unroll
        for (int ks = 0; ks < 2; ks++) {
            unsigned ad = smem_u32(Qs + (m0 + mt * 16 + (lane & 15)) * 40
                                      + ks * 16 + ((lane >> 4) << 3));
            ldsm4(qf[mt][ks][0], qf[mt][ks][1], qf[mt][ks][2], qf[mt][ks][3], ad);
        }

    float mrow[2][2] = {{-1e30f, -1e30f}, {-1e30f, -1e30f}};
    float lrow[2][2] = {{0.f, 0.f}, {0.f, 0.f}};
    float o[2][4][4];
    #pragma unroll
    for (int mt = 0; mt < 2; mt++)
        #pragma unroll
        for (int vn = 0; vn < 4; vn++)
            #pragma unroll
            for (int i = 0; i < 4; i++) o[mt][vn][i] = 0.f;

    const float* bias = g_wbias + (size_t)hh * WINN * WINN;

    for (int jc = 0; jc < WINN; jc += 32) {
        unsigned kf[4][2][2];
        #pragma unroll
        for (int np2 = 0; np2 < 2; np2++)
            #pragma unroll
            for (int ks = 0; ks < 2; ks++) {
                unsigned ad = smem_u32(Ks + (jc + np2 * 16 + ((lane >> 4) << 3) + (lane & 7)) * 40
                                          + ks * 16 + (((lane >> 3) & 1) << 3));
                unsigned r0, r1, r2, r3;
                ldsm4(r0, r1, r2, r3, ad);
                kf[2*np2][ks][0] = r0;   kf[2*np2][ks][1] = r1;
                kf[2*np2+1][ks][0] = r2; kf[2*np2+1][ks][1] = r3;
            }
        float s[2][4][4];
        #pragma unroll
        for (int mt = 0; mt < 2; mt++)
            #pragma unroll
            for (int nt = 0; nt < 4; nt++) {
                #pragma unroll
                for (int i = 0; i < 4; i++) s[mt][nt][i] = 0.f;
                #pragma unroll
                for (int ks = 0; ks < 2; ks++)
                    mma_bf(s[mt][nt], qf[mt][ks], kf[nt][ks][0], kf[nt][ks][1]);
            }
        #pragma unroll
        for (int mt = 0; mt < 2; mt++)
            #pragma unroll
            for (int h = 0; h < 2; h++) {
                int q = m0 + mt * 16 + gId + 8 * h;
                #pragma unroll
                for (int nt = 0; nt < 4; nt++) {
                    float2 bv = *(const float2*)&bias[(size_t)q * WINN + jc + nt * 8 + 2 * tig];
                    s[mt][nt][2*h]   += bv.x;
                    s[mt][nt][2*h+1] += bv.y;
                }
            }
        float co2[2][2];
        #pragma unroll
        for (int mt = 0; mt < 2; mt++)
            #pragma unroll
            for (int h = 0; h < 2; h++) {
                float rm = -1e30f;
                #pragma unroll
                for (int nt = 0; nt < 4; nt++)
                    rm = fmaxf(rm, fmaxf(s[mt][nt][2*h], s[mt][nt][2*h+1]));
                rm = fmaxf(rm, __shfl_xor_sync(0xffffffffu, rm, 1));
                rm = fmaxf(rm, __shfl_xor_sync(0xffffffffu, rm, 2));
                float mn = fmaxf(mrow[mt][h], rm);
                float co = __expf(mrow[mt][h] - mn);
                mrow[mt][h] = mn;
                float rs = 0.f;
                #pragma unroll
                for (int nt = 0; nt < 4; nt++) {
                    float e0 = __expf(s[mt][nt][2*h]   - mn);
                    float e1 = __expf(s[mt][nt][2*h+1] - mn);
                    s[mt][nt][2*h] = e0; s[mt][nt][2*h+1] = e1;
                    rs += e0 + e1;
                }
                rs += __shfl_xor_sync(0xffffffffu, rs, 1);
                rs += __shfl_xor_sync(0xffffffffu, rs, 2);
                lrow[mt][h] = lrow[mt][h] * co + rs;
                co2[mt][h] = co;
            }
        #pragma unroll
        for (int mt = 0; mt < 2; mt++)
            #pragma unroll
            for (int vn = 0; vn < 4; vn++)
                #pragma unroll
                for (int i = 0; i < 4; i++) o[mt][vn][i] *= co2[mt][i >> 1];
        #pragma unroll
        for (int ks = 0; ks < 2; ks++) {
            unsigned a[2][4];
            #pragma unroll
            for (int mt = 0; mt < 2; mt++) {
                a[mt][0] = bf2pack(s[mt][2*ks][0],   s[mt][2*ks][1]);
                a[mt][1] = bf2pack(s[mt][2*ks][2],   s[mt][2*ks][3]);
                a[mt][2] = bf2pack(s[mt][2*ks+1][0], s[mt][2*ks+1][1]);
                a[mt][3] = bf2pack(s[mt][2*ks+1][2], s[mt][2*ks+1][3]);
            }
            #pragma unroll
            for (int vn = 0; vn < 4; vn++) {
                const unsigned short* vp = Vt + (vn * 8 + gId) * VPITCH + jc + ks * 16 + 2 * tig;
                unsigned b0 = *(const unsigned*)vp;
                unsigned b1 = *(const unsigned*)(vp + 8);
                #pragma unroll
                for (int mt = 0; mt < 2; mt++)
                    mma_bf(o[mt][vn], a[mt], b0, b1);
            }
        }
    }
    #pragma unroll
    for (int mt = 0; mt < 2; mt++)
        #pragma unroll
        for (int h = 0; h < 2; h++) {
            float inv = 1.f / lrow[mt][h];
            int row = m0 + mt * 16 + gId + 8 * h;
            int ny = (wy * WS + (row >> 4)) * WW + wx * WS + (row & 15);
            unsigned short* obase = yout + ((size_t)(b * NTOK + ny)) * DIMC + hh * HD;
            #pragma unroll
            for (int vn = 0; vn < 4; vn++) {
                int vd = vn * 8 + 2 * tig;
                if (vd < HD)
                    *(unsigned*)(obase + vd) =
                        bf2pack(o[mt][vn][2*h] * inv, o[mt][vn][2*h+1] * inv);
            }
        }
}

// ---------------------------------------------------------------------------
// Gather per-token dictionary features into hc[:, 360:424] (fp32)
// ---------------------------------------------------------------------------
__global__ void gathertd_kernel(const float* __restrict__ tdproj, const int* __restrict__ tkid,
                                float* __restrict__ hc) {
    int e = blockIdx.x * blockDim.x + threadIdx.x;
    if (e < ROWS * DTD) {
        int r = e >> 6, j = e & 63;
        int b = r >> 12;
        hc[(size_t)r * CFF + MLP_HID + j] = tdproj[((size_t)b * MTOK + tkid[r]) * DTD + j];
    }
}

// ---------------------------------------------------------------------------
// Depthwise 5x5 conv + GELU + residual; fp32 hc in, bf16 hc2 out.
// ---------------------------------------------------------------------------
#define DWCH 8
__global__ void dwconv_kernel(const float* __restrict__ hc, const float* __restrict__ w,
                              const float* __restrict__ bias, unsigned short* __restrict__ hc2) {
    __shared__ float smd[20 * 20 * DWCH];
    __shared__ float wsm[25][DWCH];
    __shared__ float bsm[DWCH];
    int tid = threadIdx.x;
    int c0 = blockIdx.y * DWCH;
    int b  = blockIdx.z;
    int tileY = (blockIdx.x >> 2) * 16, tileX = (blockIdx.x & 3) * 16;
    if (tid < 200) { int t5 = tid % 25, j = tid / 25; wsm[t5][j] = w[(c0 + j) * 25 + t5]; }
    if (tid < DWCH) bsm[tid] = bias[c0 + tid];
    for (int i = tid; i < 800; i += 256) {
        int cell = i >> 1, half = i & 1;
        int cy = cell / 20, cx = cell % 20;
        int gy = tileY + cy - 2, gx = tileX + cx - 2;
        float4 v = {0.f, 0.f, 0.f, 0.f};
        if (gy >= 0 && gy < 64 && gx >= 0 && gx < 64)
            v = *(const float4*)&hc[(((size_t)b << 12) + (gy << 6) + gx) * CFF + c0 + half * 4];
        *(float4*)&smd[cell * 8 + half * 4] = v;
    }
    __syncthreads();
    int ty = tid >> 4, tx = tid & 15;
    float acc[DWCH];
    #pragma unroll
    for (int j = 0; j < DWCH; j++) acc[j] = 0.f;
    #pragma unroll
    for (int ky = 0; ky < 5; ky++) {
        #pragma unroll
        for (int kx = 0; kx < 5; kx++) {
            const float* cp = &smd[((ty + ky) * 20 + tx + kx) * 8];
            float4 a0 = *(const float4*)cp;
            float4 a1 = *(const float4*)(cp + 4);
            int t5 = ky * 5 + kx;
            acc[0] += a0.x * wsm[t5][0];
            acc[1] += a0.y * wsm[t5][1];
            acc[2] += a0.z * wsm[t5][2];
            acc[3] += a0.w * wsm[t5][3];
            acc[4] += a1.x * wsm[t5][4];
            acc[5] += a1.y * wsm[t5][5];
            acc[6] += a1.z * wsm[t5][6];
            acc[7] += a1.w * wsm[t5][7];
        }
    }
    const float* ctr = &smd[((ty + 2) * 20 + tx + 2) * 8];
    size_t idx = (((size_t)b << 12) + ((size_t)(tileY + ty) << 6) + (tileX + tx)) * CFF + c0;
    float o[8];
    #pragma unroll
    for (int j = 0; j < 8; j++) o[j] = ctr[j] + gelu_exact(acc[j] + bsm[j]);
    uint4 pk;
    pk.x = bf2pack(o[0], o[1]);
    pk.y = bf2pack(o[2], o[3]);
    pk.z = bf2pack(o[4], o[5]);
    pk.w = bf2pack(o[6], o[7]);
    *(uint4*)&hc2[idx] = pk;
}

// ---------------------------------------------------------------------------
// Launch: two-stream DAG with tensor-core winattn + acmsa (R14 structure).
// ---------------------------------------------------------------------------
extern "C" void kernel_launch(void* const* d_in, const int* in_sizes, int n_in,
                              void* d_out, int out_size) {
    const float* x        = (const float*)d_in[0];
    const float* td       = (const float*)d_in[1];
    const float* n1g      = (const float*)d_in[2];
    const float* n1b      = (const float*)d_in[3];
    const float* wqkv_w   = (const float*)d_in[4];
    const float* wqkv_b   = (const float*)d_in[5];
    const float* atd_wq_w = (const float*)d_in[6];
    const float* atd_wq_b = (const float*)d_in[7];
    const float* atd_wk_w = (const float*)d_in[8];
    const float* atd_wk_b = (const float*)d_in[9];
    const float* atd_wv_w = (const float*)d_in[10];
    const float* atd_wv_b = (const float*)d_in[11];
    const float* atd_sc   = (const float*)d_in[12];
    const float* aca_w    = (const float*)d_in[13];
    const float* aca_b    = (const float*)d_in[14];
    const float* win_rpb  = (const float*)d_in[15];
    const float* win_w    = (const float*)d_in[16];
    const float* win_b    = (const float*)d_in[17];
    const float* fctd_w   = (const float*)d_in[18];
    const float* fctd_b   = (const float*)d_in[19];
    const float* fc1_w    = (const float*)d_in[20];
    const float* fc1_b    = (const float*)d_in[21];
    const float* dw_w     = (const float*)d_in[22];
    const float* dw_b     = (const float*)d_in[23];
    const float* fc2_w    = (const float*)d_in[24];
    const float* fc2_b    = (const float*)d_in[25];
    const float* n2g      = (const float*)d_in[26];
    const float* n2b      = (const float*)d_in[27];
    const int*   rpi      = (const int*)d_in[28];
    float* out = (float*)d_out;

    float *qkv, *qatd, *kkn, *tdpr, *xsum, *hc;
    unsigned short *xn, *x2n, *yaca, *ywin, *patd, *hc2, *vvt, *wt;
    int *tkid, *sidx;
    cudaGetSymbolAddress((void**)&xn,   g_xn);
    cudaGetSymbolAddress((void**)&qkv,  g_qkv);
    cudaGetSymbolAddress((void**)&qatd, g_qatd);
    cudaGetSymbolAddress((void**)&kkn,  g_kkn);
    cudaGetSymbolAddress((void**)&vvt,  g_vvt);
    cudaGetSymbolAddress((void**)&tdpr, g_tdpr);
    cudaGetSymbolAddress((void**)&patd, g_patd);
    cudaGetSymbolAddress((void**)&yaca, g_yaca);
    cudaGetSymbolAddress((void**)&ywin, g_ywin);
    cudaGetSymbolAddress((void**)&xsum, g_xsum);
    cudaGetSymbolAddress((void**)&x2n,  g_x2n);
    cudaGetSymbolAddress((void**)&hc,   g_hc);
    cudaGetSymbolAddress((void**)&hc2,  g_hc2);
    cudaGetSymbolAddress((void**)&tkid, g_tkid);
    cudaGetSymbolAddress((void**)&sidx, g_sidx);
    cudaGetSymbolAddress((void**)&wt,   g_wt);

    static cudaStream_t s1 = nullptr;
    static cudaEvent_t eRoot, eLn1, eConvw, eWbias, eQkv, eAcmsa, eGath;
    if (!s1) {
        cudaStreamCreateWithFlags(&s1, cudaStreamNonBlocking);
        cudaEventCreateWithFlags(&eRoot,  cudaEventDisableTiming);
        cudaEventCreateWithFlags(&eLn1,   cudaEventDisableTiming);
        cudaEventCreateWithFlags(&eConvw, cudaEventDisableTiming);
        cudaEventCreateWithFlags(&eWbias, cudaEventDisableTiming);
        cudaEventCreateWithFlags(&eQkv,   cudaEventDisableTiming);
        cudaEventCreateWithFlags(&eAcmsa, cudaEventDisableTiming);
        cudaEventCreateWithFlags(&eGath,  cudaEventDisableTiming);
        cudaFuncSetAttribute(winattn_tc, cudaFuncAttributeMaxDynamicSharedMemorySize, WSMEM);
    }

    // ---- fork side stream from main ----
    cudaEventRecord(eRoot, 0);
    cudaStreamWaitEvent(s1, eRoot, 0);

    // ---- side stream: prologue kernels ----
    convw_all<<<(S_TOT + 255)/256, 256, 0, s1>>>(wqkv_w, aca_w, win_w, fc1_w, fc2_w, wt);
    cudaEventRecord(eConvw, s1);
    wbias_kernel<<<WINN*WINN/256, 256, 0, s1>>>(rpi, win_rpb);
    cudaEventRecord(eWbias, s1);
    dict_kernel<<<BATCH*MTOK, 256, 0, s1>>>(td, atd_wk_w, atd_wk_b, atd_wv_w, atd_wv_b,
                                            fctd_w, fctd_b, kkn, vvt, tdpr);

    // ---- main stream: LN1 (+ fused q_atd) ----
    ln_kernel<<<ROWS/8, 256>>>(x, n1g, n1b, xn, atd_wq_w, atd_wq_b, qatd);
    cudaEventRecord(eLn1, 0);

    // main: qkv GEMM (needs convw)
    cudaStreamWaitEvent(0, eConvw, 0);
    gemm_bf<<<dim3(9, ROWS/128), 256>>>(xn, wt + WT_QKV, DIMC, nullptr, nullptr, 0,
                                        nullptr, nullptr, 0, 0,
                                        wqkv_b, nullptr, nullptr,
                                        qkv, ROWS, QKVW, QKVW, 0);
    cudaEventRecord(eQkv, 0);

    // main: tensor-core window attention (needs qkv + wbias)
    cudaStreamWaitEvent(0, eWbias, 0);
    winattn_tc<<<NWIN*HEADS, 256, WSMEM>>>(qkv, ywin);

    // ---- side stream: ATD chain (needs ln1; acmsa needs qkv) ----
    cudaStreamWaitEvent(s1, eLn1, 0);
    atd_kernel<<<ROWS/8, 256, 0, s1>>>(qatd, kkn, atd_sc, patd, tkid);
    sortscatter_kernel<<<BATCH*MTOK, 256, 0, s1>>>(tkid, sidx);
    cudaStreamWaitEvent(s1, eQkv, 0);
    acmsa_tc<<<BATCH*NG*HEADS, 128, 0, s1>>>(qkv, sidx, yaca);
    cudaEventRecord(eAcmsa, s1);
    gathertd_kernel<<<ROWS*DTD/256, 256, 0, s1>>>(tdpr, tkid, hc);
    cudaEventRecord(eGath, s1);

    // ---- main stream: join acmsa branch, fused residual GEMM ----
    cudaStreamWaitEvent(0, eAcmsa, 0);
    gemm_bf<<<dim3(3, ROWS/128), 256>>>(yaca, wt + WT_ACA, DIMC, ywin, wt + WT_WIN, DIMC,
                                        patd, vvt, (long)DIMC*MTOK, MTOK,
                                        aca_b, win_b, x,
                                        xsum, ROWS, DIMC, DIMC, 0);
    ln_kernel<<<ROWS/8, 256>>>(xsum, n2g, n2b, x2n, nullptr, nullptr, nullptr);
    gemm_bf<<<dim3(6, ROWS/128), 256>>>(x2n, wt + WT_FC1, DIMC, nullptr, nullptr, 0,
                                        nullptr, nullptr, 0, 0,
                                        fc1_b, nullptr, nullptr,
                                        hc, ROWS, MLP_HID, CFF, 1);
    cudaStreamWaitEvent(0, eGath, 0);
    dwconv_kernel<<<dim3(16, CFF/DWCH, BATCH), 256>>>(hc, dw_w, dw_b, hc2);
    gemm_bf<<<dim3(3, ROWS/128), 256>>>(hc2, wt + WT_FC2, CFF, nullptr, nullptr, 0,
                                        nullptr, nullptr, 0, 0,
                                        fc2_b, nullptr, xsum,
                                        out, ROWS, DIMC, DIMC, 0);
}

// round 17
// speedup vs baseline: 1.0670x; 1.0539x over previous
#include <cuda_runtime.h>
#include <cuda_bf16.h>
#include <math.h>

// ---------------------------------------------------------------------------
// Problem constants
// ---------------------------------------------------------------------------
#define BATCH 8
#define NTOK 4096
#define ROWS (BATCH*NTOK)
#define DIMC 180
#define HEADS 6
#define HD 30
#define QKVW 540
#define MTOK 64
#define RDIM 10
#define GS 128
#define NG 32
#define WS 16
#define WINN 256
#define NWIN 128
#define MLP_HID 360
#define DTD 64
#define CFF 424
#define HH 64
#define WW 64

// bf16 weight scratch offsets (elements)
#define WT_QKV 0
#define WT_ACA (WT_QKV + DIMC*QKVW)
#define WT_WIN (WT_ACA + DIMC*DIMC)
#define WT_FC1 (WT_WIN + DIMC*DIMC)
#define WT_FC2 (WT_FC1 + DIMC*MLP_HID)
#define WT_TOTAL (WT_FC2 + CFF*DIMC)

// ---------------------------------------------------------------------------
// Scratch
// ---------------------------------------------------------------------------
__device__ unsigned short g_xn  [ROWS*DIMC];        // bf16
__device__ unsigned short g_qkv [ROWS*QKVW];        // bf16 (was fp32)
__device__ float g_qatd [ROWS*RDIM];
__device__ float g_kkn  [BATCH*MTOK*RDIM];
__device__ unsigned short g_vvt [BATCH*DIMC*MTOK];  // bf16, transposed [b][n][m]
__device__ float g_tdpr [BATCH*MTOK*DTD];
__device__ unsigned short g_patd[ROWS*MTOK];        // bf16
__device__ int   g_tkid [ROWS];
__device__ int   g_sidx [ROWS];
__device__ unsigned short g_yaca[ROWS*DIMC];        // bf16
__device__ unsigned short g_ywin[ROWS*DIMC];        // bf16
__device__ float g_xsum [ROWS*DIMC];
__device__ unsigned short g_x2n [ROWS*DIMC];        // bf16
__device__ float g_hc   [ROWS*CFF];                 // fp32
__device__ unsigned short g_hc2 [ROWS*CFF];         // bf16
__device__ float g_wbias[HEADS*WINN*WINN];
__device__ unsigned short g_wt  [WT_TOTAL];         // bf16 transposed weights

// ---------------------------------------------------------------------------
// Helpers
// ---------------------------------------------------------------------------
__device__ __forceinline__ float warp_sum(float v) {
    #pragma unroll
    for (int o = 16; o; o >>= 1) v += __shfl_xor_sync(0xffffffffu, v, o);
    return v;
}
__device__ __forceinline__ float gelu_exact(float v) {
    return 0.5f * v * (1.0f + erff(v * 0.70710678118654752440f));
}
__device__ __forceinline__ unsigned smem_u32(const void* p) {
    return (unsigned)__cvta_generic_to_shared(p);
}
__device__ __forceinline__ unsigned short f2bf(float v) {
    __nv_bfloat16 h = __float2bfloat16_rn(v);
    return *(unsigned short*)&h;
}
__device__ __forceinline__ unsigned bf2pack(float lo, float hi) {
    __nv_bfloat162 h = __floats2bfloat162_rn(lo, hi);
    return *(unsigned*)&h;
}
__device__ __forceinline__ void ldsm4(unsigned& r0, unsigned& r1, unsigned& r2, unsigned& r3,
                                      unsigned addr) {
    asm volatile("ldmatrix.sync.aligned.m8n8.x4.shared.b16 {%0,%1,%2,%3}, [%4];"
                 : "=r"(r0), "=r"(r1), "=r"(r2), "=r"(r3) : "r"(addr));
}
__device__ __forceinline__ void mma_bf(float* d, const unsigned* a, unsigned b0, unsigned b1) {
    asm volatile(
        "mma.sync.aligned.m16n8k16.row.col.f32.bf16.bf16.f32 "
        "{%0,%1,%2,%3},{%4,%5,%6,%7},{%8,%9},{%0,%1,%2,%3};"
        : "+f"(d[0]), "+f"(d[1]), "+f"(d[2]), "+f"(d[3])
        : "r"(a[0]), "r"(a[1]), "r"(a[2]), "r"(a[3]), "r"(b0), "r"(b1));
}

// ---------------------------------------------------------------------------
// Merged weight transpose+convert for all five GEMM weights.
// ---------------------------------------------------------------------------
#define S_QKV (DIMC*QKVW)
#define S_ACA (DIMC*DIMC)
#define S_WIN (DIMC*DIMC)
#define S_FC1 (DIMC*MLP_HID)
#define S_FC2 (CFF*DIMC)
#define S_TOT (S_QKV+S_ACA+S_WIN+S_FC1+S_FC2)

__global__ void convw_all(const float* __restrict__ qkv_w, const float* __restrict__ aca_w,
                          const float* __restrict__ win_w, const float* __restrict__ fc1_w,
                          const float* __restrict__ fc2_w, unsigned short* __restrict__ wt) {
    int i = blockIdx.x * blockDim.x + threadIdx.x;
    if (i >= S_TOT) return;
    const float* W; int K, N, loc, base;
    if (i < S_QKV)                       { W = qkv_w; K = DIMC; N = QKVW;   loc = i;                         base = WT_QKV; }
    else if (i < S_QKV+S_ACA)            { W = aca_w; K = DIMC; N = DIMC;   loc = i - S_QKV;                 base = WT_ACA; }
    else if (i < S_QKV+S_ACA+S_WIN)      { W = win_w; K = DIMC; N = DIMC;   loc = i - S_QKV - S_ACA;         base = WT_WIN; }
    else if (i < S_QKV+S_ACA+S_WIN+S_FC1){ W = fc1_w; K = DIMC; N = MLP_HID;loc = i - S_QKV - S_ACA - S_WIN; base = WT_FC1; }
    else                                 { W = fc2_w; K = CFF;  N = DIMC;   loc = i - S_QKV-S_ACA-S_WIN-S_FC1; base = WT_FC2; }
    int n = loc / K, k = loc % K;
    wt[base + loc] = f2bf(W[(size_t)k * N + n]);
}

// ---------------------------------------------------------------------------
// Fused dictionary projections: kkn fp32 l2n, vvt bf16 transposed, tdpr fp32
// ---------------------------------------------------------------------------
__global__ void dict_kernel(const float* __restrict__ td,
                            const float* __restrict__ wk_w, const float* __restrict__ wk_b,
                            const float* __restrict__ wv_w, const float* __restrict__ wv_b,
                            const float* __restrict__ ftd_w, const float* __restrict__ ftd_b,
                            float* __restrict__ kkn, unsigned short* __restrict__ vvt,
                            float* __restrict__ tdpr) {
    int r = blockIdx.x;                 // 0..511
    int b = r >> 6, m = r & 63;
    __shared__ float as[DIMC];
    __shared__ float kbuf[RDIM];
    int tid = threadIdx.x;
    const float* ar = td + (size_t)r * DIMC;
    if (tid < DIMC) as[tid] = ar[tid];
    __syncthreads();
    if (tid < DIMC) {
        float acc = wv_b[tid];
        #pragma unroll 4
        for (int k = 0; k < DIMC; k++) acc += as[k] * wv_w[(size_t)k * DIMC + tid];
        vvt[((size_t)b * DIMC + tid) * MTOK + m] = f2bf(acc);
    } else if (tid < DIMC + DTD) {
        int c = tid - DIMC;
        float acc = ftd_b[c];
        #pragma unroll 4
        for (int k = 0; k < DIMC; k++) acc += as[k] * ftd_w[(size_t)k * DTD + c];
        tdpr[(size_t)r * DTD + c] = acc;
    } else if (tid < DIMC + DTD + RDIM) {
        int c = tid - DIMC - DTD;
        float acc = wk_b[c];
        #pragma unroll 4
        for (int k = 0; k < DIMC; k++) acc += as[k] * wk_w[(size_t)k * RDIM + c];
        kbuf[c] = acc;
    }
    __syncthreads();
    if (tid >= DIMC + DTD && tid < DIMC + DTD + RDIM) {
        int c = tid - DIMC - DTD;
        float ss = 0.f;
        #pragma unroll
        for (int j = 0; j < RDIM; j++) ss += kbuf[j] * kbuf[j];
        float inv = 1.f / fmaxf(sqrtf(ss), 1e-12f);
        kkn[(size_t)r * RDIM + c] = kbuf[c] * inv;
    }
}

// ---------------------------------------------------------------------------
// Window attention bias expansion
// ---------------------------------------------------------------------------
__global__ void wbias_kernel(const int* __restrict__ rpi, const float* __restrict__ rpb) {
    int e = blockIdx.x * blockDim.x + threadIdx.x;
    if (e < WINN * WINN) {
        int idx = rpi[e];
        #pragma unroll
        for (int h = 0; h < HEADS; h++) g_wbias[h * WINN * WINN + e] = rpb[idx * HEADS + h];
    }
}

// ---------------------------------------------------------------------------
// LayerNorm -> bf16 out (+ optional fused 10-dim q projection, fp32).
// ---------------------------------------------------------------------------
__global__ void ln_kernel(const float* __restrict__ x, const float* __restrict__ g,
                          const float* __restrict__ b, unsigned short* __restrict__ out,
                          const float* __restrict__ wq, const float* __restrict__ bq,
                          float* __restrict__ qout) {
    __shared__ float ws[1920];
    __shared__ float bqs[16];
    int tid = threadIdx.x;
    if (wq) {
        for (int i = tid; i < 1920; i += 256) ws[i] = (i < DIMC * RDIM) ? wq[i] : 0.f;
        if (tid < RDIM) bqs[tid] = bq[tid];
        __syncthreads();
    }
    int row = (blockIdx.x * blockDim.x + tid) >> 5;
    if (row >= ROWS) return;
    int lane = tid & 31;
    const float2* xr = (const float2*)(x + (size_t)row * DIMC);   // 90 float2
    float2 v[3];
    float s = 0.f, s2 = 0.f;
    #pragma unroll
    for (int k = 0; k < 3; k++) {
        int idx = lane + k * 32;
        v[k] = (idx < 90) ? xr[idx] : make_float2(0.f, 0.f);
        s += v[k].x + v[k].y;
        s2 += v[k].x * v[k].x + v[k].y * v[k].y;
    }
    s = warp_sum(s); s2 = warp_sum(s2);
    float mu = s * (1.f / DIMC);
    float var = s2 * (1.f / DIMC) - mu * mu;
    float rstd = rsqrtf(var + 1e-5f);
    float2 nv[3];
    unsigned* orow = (unsigned*)(out + (size_t)row * DIMC);
    const float2* g2 = (const float2*)g;
    const float2* b2 = (const float2*)b;
    #pragma unroll
    for (int k = 0; k < 3; k++) {
        int idx = lane + k * 32;
        if (idx < 90) {
            float2 gg = g2[idx], bb = b2[idx];
            nv[k].x = (v[k].x - mu) * rstd * gg.x + bb.x;
            nv[k].y = (v[k].y - mu) * rstd * gg.y + bb.y;
            orow[idx] = bf2pack(nv[k].x, nv[k].y);
        } else {
            nv[k] = make_float2(0.f, 0.f);
        }
    }
    if (wq) {
        float myq = 0.f;
        #pragma unroll
        for (int o = 0; o < RDIM; o++) {
            float p = 0.f;
            #pragma unroll
            for (int k = 0; k < 3; k++) {
                int idx = lane + k * 32;
                p += nv[k].x * ws[(2 * idx) * RDIM + o]
                   + nv[k].y * ws[(2 * idx + 1) * RDIM + o];
            }
            p = warp_sum(p);
            if (lane == o) myq = p + bqs[o];
        }
        if (lane < RDIM) qout[(size_t)row * RDIM + lane] = myq;
    }
}

// ---------------------------------------------------------------------------
// bf16 tensor-core GEMM (m16n8k16) with ldmatrix fragment loads.
// Output: fp32 C (full epilogue) or bf16 Cb (bias+act, paired stores).
// ---------------------------------------------------------------------------
struct GPass { const unsigned short* A; const unsigned short* W; int K; int kt; };

__global__ __launch_bounds__(256) void gemm_bf(
        const unsigned short* __restrict__ A1, const unsigned short* __restrict__ W1, int K1,
        const unsigned short* __restrict__ A2, const unsigned short* __restrict__ W2, int K2,
        const unsigned short* __restrict__ A3, const unsigned short* __restrict__ W3base,
        long w3_stride, int K3,
        const float* __restrict__ b1, const float* __restrict__ b2,
        const float* __restrict__ add1,
        float* __restrict__ C, unsigned short* __restrict__ Cb,
        int M, int N, int ldc, int act) {
    __shared__ unsigned short As[2][128][40];
    __shared__ unsigned short Ws[2][64][40];
    int tid  = threadIdx.x;
    int lane = tid & 31;
    int warp = tid >> 5;
    int warpM = warp & 3;
    int warpN = warp >> 2;
    int gId = lane >> 2;
    int tig = lane & 3;
    int row0 = blockIdx.y * 128;
    int col0 = blockIdx.x * 64;

    GPass ps[3];
    int np = 0;
    if (A1 && K1 > 0) ps[np++] = {A1, W1, K1, (K1 + 31) >> 5};
    if (A2 && K2 > 0) ps[np++] = {A2, W2, K2, (K2 + 31) >> 5};
    if (A3 && K3 > 0) ps[np++] = {A3, W3base + (size_t)(row0 >> 12) * w3_stride, K3, (K3 + 31) >> 5};
    int total = 0;
    for (int p = 0; p < np; p++) total += ps[p].kt;

    auto copy_tile = [&](int gi, int buf) {
        int p = 0, loc = gi;
        while (loc >= ps[p].kt) { loc -= ps[p].kt; p++; }
        const unsigned short* A = ps[p].A;
        const unsigned short* W = ps[p].W;
        int K = ps[p].K;
        int k0 = loc << 5;
        #pragma unroll
        for (int f = 0; f < 4; f++) {
            int c = tid + f * 256;
            int m = c >> 3, kc = (c & 7) << 2;
            int gk = k0 + kc;
            int rem = K - gk;
            int bytes = (rem <= 0) ? 0 : ((rem >= 4) ? 8 : rem * 2);
            const unsigned short* src = bytes ? (A + (size_t)(row0 + m) * K + gk) : A;
            unsigned dst = smem_u32(&As[buf][m][kc]);
            asm volatile("cp.async.ca.shared.global [%0], [%1], 8, %2;"
                         :: "r"(dst), "l"(src), "r"(bytes));
        }
        #pragma unroll
        for (int f = 0; f < 2; f++) {
            int c = tid + f * 256;
            int n = c >> 3, kc = (c & 7) << 2;
            int gn = col0 + n, gk = k0 + kc;
            int bytes = 0;
            if (gn < N) {
                int rem = K - gk;
                bytes = (rem <= 0) ? 0 : ((rem >= 4) ? 8 : rem * 2);
            }
            const unsigned short* src = bytes ? (W + (size_t)gn * K + gk) : W;
            unsigned dst = smem_u32(&Ws[buf][n][kc]);
            asm volatile("cp.async.ca.shared.global [%0], [%1], 8, %2;"
                         :: "r"(dst), "l"(src), "r"(bytes));
        }
    };

    float d[2][4][4];
    #pragma unroll
    for (int mt = 0; mt < 2; mt++)
        #pragma unroll
        for (int nt = 0; nt < 4; nt++)
            #pragma unroll
            for (int i = 0; i < 4; i++) d[mt][nt][i] = 0.f;

    copy_tile(0, 0);
    asm volatile("cp.async.commit_group;");
    for (int i = 0; i < total; i++) {
        asm volatile("cp.async.wait_group 0;");
        __syncthreads();
        if (i + 1 < total) {
            copy_tile(i + 1, (i + 1) & 1);
            asm volatile("cp.async.commit_group;");
        }
        int buf = i & 1;
        #pragma unroll
        for (int ks = 0; ks < 2; ks++) {
            int kb = ks * 16;
            unsigned a[2][4], bfr[4][2];
            int arow = lane & 15;
            int acol = kb + ((lane >> 4) << 3);
            #pragma unroll
            for (int mt = 0; mt < 2; mt++) {
                int m0 = warpM * 32 + mt * 16;
                unsigned ad = smem_u32(&As[buf][m0 + arow][acol]);
                ldsm4(a[mt][0], a[mt][1], a[mt][2], a[mt][3], ad);
            }
            int wrow = ((lane >> 4) << 3) + (lane & 7);
            int wcol = kb + (((lane >> 3) & 1) << 3);
            #pragma unroll
            for (int np2 = 0; np2 < 2; np2++) {
                int n0 = warpN * 32 + np2 * 16;
                unsigned ad = smem_u32(&Ws[buf][n0 + wrow][wcol]);
                unsigned r0, r1, r2, r3;
                ldsm4(r0, r1, r2, r3, ad);
                bfr[2*np2][0] = r0;  bfr[2*np2][1] = r1;
                bfr[2*np2+1][0] = r2; bfr[2*np2+1][1] = r3;
            }
            #pragma unroll
            for (int mt = 0; mt < 2; mt++)
                #pragma unroll
                for (int nt = 0; nt < 4; nt++)
                    mma_bf(d[mt][nt], a[mt], bfr[nt][0], bfr[nt][1]);
        }
    }

    if (Cb) {
        #pragma unroll
        for (int mt = 0; mt < 2; mt++)
            #pragma unroll
            for (int nt = 0; nt < 4; nt++)
                #pragma unroll
                for (int h = 0; h < 2; h++) {
                    int r = row0 + warpM * 32 + mt * 16 + gId + h * 8;
                    int c = col0 + warpN * 32 + nt * 8 + tig * 2;
                    if (c < N) {
                        float v0 = d[mt][nt][2*h], v1 = d[mt][nt][2*h+1];
                        if (b1) { v0 += b1[c]; v1 += b1[c+1]; }
                        if (act) { v0 = gelu_exact(v0); v1 = gelu_exact(v1); }
                        *(unsigned*)&Cb[(size_t)r * ldc + c] = bf2pack(v0, v1);
                    }
                }
    } else {
        #pragma unroll
        for (int mt = 0; mt < 2; mt++) {
            #pragma unroll
            for (int nt = 0; nt < 4; nt++) {
                #pragma unroll
                for (int i = 0; i < 4; i++) {
                    int r = row0 + warpM * 32 + mt * 16 + gId + (i >> 1) * 8;
                    int c = col0 + warpN * 32 + nt * 8 + tig * 2 + (i & 1);
                    if (c < N) {
                        float v = d[mt][nt][i];
                        if (b1)   v += b1[c];
                        if (b2)   v += b2[c];
                        if (add1) v += add1[(size_t)r * N + c];
                        if (act)  v = gelu_exact(v);
                        C[(size_t)r * ldc + c] = v;
                    }
                }
            }
        }
    }
}

// ---------------------------------------------------------------------------
// ATD: softmax probs P (bf16) + argmax tkid. One warp per token. fp32 math.
// ---------------------------------------------------------------------------
__global__ void atd_kernel(const float* __restrict__ qatd, const float* __restrict__ kkn,
                           const float* __restrict__ scale,
                           unsigned short* __restrict__ P, int* __restrict__ tkid) {
    int t = (blockIdx.x * blockDim.x + threadIdx.x) >> 5;
    int lane = threadIdx.x & 31;
    if (t >= ROWS) return;
    int b = t >> 12;
    float q = (lane < RDIM) ? qatd[(size_t)t * RDIM + lane] : 0.f;
    float ss = warp_sum(q * q);
    float qn = q * (1.f / fmaxf(sqrtf(ss), 1e-12f));
    const float* kb = kkn + (size_t)b * MTOK * RDIM;
    float s0 = 0.f, s1 = 0.f;
    #pragma unroll
    for (int d = 0; d < RDIM; d++) {
        float qd = __shfl_sync(0xffffffffu, qn, d);
        s0 += qd * kb[lane * RDIM + d];
        s1 += qd * kb[(lane + 32) * RDIM + d];
    }
    float sc = fminf(fmaxf(scale[0], 0.f), 3.f);
    float ls = 1.f + sc * 4.15888308335967186f;  // log(64)
    s0 *= ls; s1 *= ls;
    float mv = fmaxf(s0, s1);
    int mi = (s0 >= s1) ? lane : lane + 32;
    #pragma unroll
    for (int o = 16; o; o >>= 1) {
        float ov = __shfl_xor_sync(0xffffffffu, mv, o);
        int   oi = __shfl_xor_sync(0xffffffffu, mi, o);
        if (ov > mv || (ov == mv && oi < mi)) { mv = ov; mi = oi; }
    }
    float p0 = __expf(s0 - mv), p1 = __expf(s1 - mv);
    float sum = warp_sum(p0 + p1);
    float inv = 1.f / sum;
    P[(size_t)t * MTOK + lane]      = f2bf(p0 * inv);
    P[(size_t)t * MTOK + lane + 32] = f2bf(p1 * inv);
    if (lane == 0) tkid[t] = mi;
}

// ---------------------------------------------------------------------------
// Single-pass stable counting sort scatter: block = (batch, bin).
// ---------------------------------------------------------------------------
__global__ void sortscatter_kernel(const int* __restrict__ tkid, int* __restrict__ sidx) {
    int b = blockIdx.x >> 6, bin = blockIdx.x & 63;
    const int* tk = tkid + b * NTOK;
    __shared__ int sc[256];
    int t = threadIdx.x;
    int start = t * 16;
    int eq = 0, less = 0;
    int vals[16];
    #pragma unroll
    for (int k = 0; k < 16; k++) {
        vals[k] = tk[start + k];
        eq += (vals[k] == bin);
        less += (vals[k] < bin);
    }
    sc[t] = (less << 16) | eq;
    __syncthreads();
    #pragma unroll
    for (int d = 1; d < 256; d <<= 1) {
        int v = (t >= d) ? sc[t - d] : 0;
        __syncthreads();
        sc[t] += v;
        __syncthreads();
    }
    int base = sc[255] >> 16;
    int pos = base + (sc[t] & 0xffff) - eq;
    #pragma unroll
    for (int k = 0; k < 16; k++)
        if (vals[k] == bin) sidx[b * NTOK + pos++] = start + k;
}

// ---------------------------------------------------------------------------
// Tensor-core AC_MSA grouped attention (flash-style, gathered rows).
// qkv is bf16; Q unscaled in smem, scale applied to S in fp32.
// ---------------------------------------------------------------------------
#define APITCH 136

__global__ __launch_bounds__(128) void acmsa_tc(
        const unsigned short* __restrict__ qkv, const int* __restrict__ sidx,
        unsigned short* __restrict__ yout) {
    __shared__ unsigned short Qs[GS * 40];
    __shared__ unsigned short Ks[GS * 40];
    __shared__ unsigned short Vt[32 * APITCH];
    int bi = blockIdx.x;
    int hh = bi % HEADS;
    int g  = (bi / HEADS) % NG;
    int b  = bi / (HEADS * NG);
    int lane = threadIdx.x & 31;
    int warp = threadIdx.x >> 5;               // 0..3
    const float scale = 0.18257418583505536f;  // 30^-0.5
    const int* sb = sidx + b * NTOK + g * GS;

    #pragma unroll 4
    for (int u = 0; u < 32; u++) {
        int r = warp * 32 + u;
        int tok = sb[r];
        size_t rb = ((size_t)(b * NTOK + tok)) * QKVW + hh * HD;
        unsigned short qv = 0, kv = 0, vv = 0;
        if (lane < HD) {
            qv = qkv[rb + lane];
            kv = qkv[rb + 180 + lane];
            vv = qkv[rb + 360 + lane];
        }
        Qs[r * 40 + lane] = qv;
        Ks[r * 40 + lane] = kv;
        Vt[lane * APITCH + r] = vv;
    }
    __syncthreads();

    int gId = lane >> 2, tig = lane & 3;
    int m0 = warp * 32;

    unsigned qf[2][2][4];
    #pragma unroll
    for (int mt = 0; mt < 2; mt++)
        #pragma unroll
        for (int ks = 0; ks < 2; ks++) {
            unsigned ad = smem_u32(Qs + (m0 + mt * 16 + (lane & 15)) * 40
                                      + ks * 16 + ((lane >> 4) << 3));
            ldsm4(qf[mt][ks][0], qf[mt][ks][1], qf[mt][ks][2], qf[mt][ks][3], ad);
        }

    float mrow[2][2] = {{-1e30f, -1e30f}, {-1e30f, -1e30f}};
    float lrow[2][2] = {{0.f, 0.f}, {0.f, 0.f}};
    float o[2][4][4];
    #pragma unroll
    for (int mt = 0; mt < 2; mt++)
        #pragma unroll
        for (int vn = 0; vn < 4; vn++)
            #pragma unroll
            for (int i = 0; i < 4; i++) o[mt][vn][i] = 0.f;

    for (int jc = 0; jc < GS; jc += 32) {
        unsigned kf[4][2][2];
        #pragma unroll
        for (int np2 = 0; np2 < 2; np2++)
            #pragma unroll
            for (int ks = 0; ks < 2; ks++) {
                unsigned ad = smem_u32(Ks + (jc + np2 * 16 + ((lane >> 4) << 3) + (lane & 7)) * 40
                                          + ks * 16 + (((lane >> 3) & 1) << 3));
                unsigned r0, r1, r2, r3;
                ldsm4(r0, r1, r2, r3, ad);
                kf[2*np2][ks][0] = r0;   kf[2*np2][ks][1] = r1;
                kf[2*np2+1][ks][0] = r2; kf[2*np2+1][ks][1] = r3;
            }
        float s[2][4][4];
        #pragma unroll
        for (int mt = 0; mt < 2; mt++)
            #pragma unroll
            for (int nt = 0; nt < 4; nt++) {
                #pragma unroll
                for (int i = 0; i < 4; i++) s[mt][nt][i] = 0.f;
                #pragma unroll
                for (int ks = 0; ks < 2; ks++)
                    mma_bf(s[mt][nt], qf[mt][ks], kf[nt][ks][0], kf[nt][ks][1]);
                #pragma unroll
                for (int i = 0; i < 4; i++) s[mt][nt][i] *= scale;
            }
        float co2[2][2];
        #pragma unroll
        for (int mt = 0; mt < 2; mt++)
            #pragma unroll
            for (int h = 0; h < 2; h++) {
                float rm = -1e30f;
                #pragma unroll
                for (int nt = 0; nt < 4; nt++)
                    rm = fmaxf(rm, fmaxf(s[mt][nt][2*h], s[mt][nt][2*h+1]));
                rm = fmaxf(rm, __shfl_xor_sync(0xffffffffu, rm, 1));
                rm = fmaxf(rm, __shfl_xor_sync(0xffffffffu, rm, 2));
                float mn = fmaxf(mrow[mt][h], rm);
                float co = __expf(mrow[mt][h] - mn);
                mrow[mt][h] = mn;
                float rs = 0.f;
                #pragma unroll
                for (int nt = 0; nt < 4; nt++) {
                    float e0 = __expf(s[mt][nt][2*h]   - mn);
                    float e1 = __expf(s[mt][nt][2*h+1] - mn);
                    s[mt][nt][2*h] = e0; s[mt][nt][2*h+1] = e1;
                    rs += e0 + e1;
                }
                rs += __shfl_xor_sync(0xffffffffu, rs, 1);
                rs += __shfl_xor_sync(0xffffffffu, rs, 2);
                lrow[mt][h] = lrow[mt][h] * co + rs;
                co2[mt][h] = co;
            }
        #pragma unroll
        for (int mt = 0; mt < 2; mt++)
            #pragma unroll
            for (int vn = 0; vn < 4; vn++)
                #pragma unroll
                for (int i = 0; i < 4; i++) o[mt][vn][i] *= co2[mt][i >> 1];
        #pragma unroll
        for (int ks = 0; ks < 2; ks++) {
            unsigned a[2][4];
            #pragma unroll
            for (int mt = 0; mt < 2; mt++) {
                a[mt][0] = bf2pack(s[mt][2*ks][0],   s[mt][2*ks][1]);
                a[mt][1] = bf2pack(s[mt][2*ks][2],   s[mt][2*ks][3]);
                a[mt][2] = bf2pack(s[mt][2*ks+1][0], s[mt][2*ks+1][1]);
                a[mt][3] = bf2pack(s[mt][2*ks+1][2], s[mt][2*ks+1][3]);
            }
            #pragma unroll
            for (int vn = 0; vn < 4; vn++) {
                const unsigned short* vp = Vt + (vn * 8 + gId) * APITCH + jc + ks * 16 + 2 * tig;
                unsigned b0 = *(const unsigned*)vp;
                unsigned b1 = *(const unsigned*)(vp + 8);
                #pragma unroll
                for (int mt = 0; mt < 2; mt++)
                    mma_bf(o[mt][vn], a[mt], b0, b1);
            }
        }
    }
    #pragma unroll
    for (int mt = 0; mt < 2; mt++)
        #pragma unroll
        for (int h = 0; h < 2; h++) {
            float inv = 1.f / lrow[mt][h];
            int row = m0 + mt * 16 + gId + 8 * h;
            int tok = sb[row];
            unsigned short* obase = yout + ((size_t)(b * NTOK + tok)) * DIMC + hh * HD;
            #pragma unroll
            for (int vn = 0; vn < 4; vn++) {
                int vd = vn * 8 + 2 * tig;
                if (vd < HD)
                    *(unsigned*)(obase + vd) =
                        bf2pack(o[mt][vn][2*h] * inv, o[mt][vn][2*h+1] * inv);
            }
        }
}

// ---------------------------------------------------------------------------
// Tensor-core window attention (flash-style). qkv bf16; scale folded into S.
// ---------------------------------------------------------------------------
#define VPITCH 264
#define WSMEM ((2*256*40 + 32*VPITCH) * 2)   // 57856 bytes

__global__ __launch_bounds__(256) void winattn_tc(const unsigned short* __restrict__ qkv,
                                                  unsigned short* __restrict__ yout) {
    extern __shared__ unsigned short sm16[];
    unsigned short* Qs = sm16;                 // [256][40]
    unsigned short* Ks = sm16 + 256 * 40;      // [256][40]
    unsigned short* Vt = sm16 + 2 * 256 * 40;  // [32][VPITCH]
    int bi = blockIdx.x;
    int hh = bi % HEADS;
    int wdx = bi / HEADS;
    int b = wdx >> 4;
    int wy = (wdx >> 2) & 3;
    int wx = wdx & 3;
    int lane = threadIdx.x & 31;
    int warp = threadIdx.x >> 5;               // 0..7
    const float scale = 0.18257418583505536f;  // 30^-0.5

    #pragma unroll 4
    for (int u = 0; u < 32; u++) {
        int r = warp * 32 + u;
        int ny = (wy * WS + (r >> 4)) * WW + wx * WS + (r & 15);
        size_t rb = ((size_t)(b * NTOK + ny)) * QKVW + hh * HD;
        unsigned short qv = 0, kv = 0, vv = 0;
        if (lane < HD) {
            qv = qkv[rb + lane];
            kv = qkv[rb + 180 + lane];
            vv = qkv[rb + 360 + lane];
        }
        Qs[r * 40 + lane] = qv;
        Ks[r * 40 + lane] = kv;
        Vt[lane * VPITCH + r] = vv;
    }
    __syncthreads();

    int gId = lane >> 2, tig = lane & 3;
    int m0 = warp * 32;

    unsigned qf[2][2][4];
    #pragma unroll
    for (int mt = 0; mt < 2; mt++)
        #pragma unroll
        for (int ks = 0; ks < 2; ks++) {
            unsigned ad = smem_u32(Qs + (m0 + mt * 16 + (lane & 15)) * 40
                                      + ks * 16 + ((lane >> 4) << 3));
            ldsm4(qf[mt][ks][0], qf[mt][ks][1], qf[mt][ks][2], qf[mt][ks][3], ad);
        }

    float mrow[2][2] = {{-1e30f, -1e30f}, {-1e30f, -1e30f}};
    float lrow[2][2] = {{0.f, 0.f}, {0.f, 0.f}};
    float o[2][4][4];
    #pragma unroll
    for (int mt = 0; mt < 2; mt++)
        #pragma unroll
        for (int vn = 0; vn < 4; vn++)
            #pragma unroll
            for (int i = 0; i < 4; i++) o[mt][vn][i] = 0.f;

    const float* bias = g_wbias + (size_t)hh * WINN * WINN;

    for (int jc = 0; jc < WINN; jc += 32) {
        unsigned kf[4][2][2];
        #pragma unroll
        for (int np2 = 0; np2 < 2; np2++)
            #pragma unroll
            for (int ks = 0; ks < 2; ks++) {
                unsigned ad = smem_u32(Ks + (jc + np2 * 16 + ((lane >> 4) << 3) + (lane & 7)) * 40
                                          + ks * 16 + (((lane >> 3) & 1) << 3));
                unsigned r0, r1, r2, r3;
                ldsm4(r0, r1, r2, r3, ad);
                kf[2*np2][ks][0] = r0;   kf[2*np2][ks][1] = r1;
                kf[2*np2+1][ks][0] = r2; kf[2*np2+1][ks][1] = r3;
            }
        float s[2][4][4];
        #pragma unroll
        for (int mt = 0; mt < 2; mt++)
            #pragma unroll
            for (int nt = 0; nt < 4; nt++) {
                #pragma unroll
                for (int i = 0; i < 4; i++) s[mt][nt][i] = 0.f;
                #pragma unroll
                for (int ks = 0; ks < 2; ks++)
                    mma_bf(s[mt][nt], qf[mt][ks], kf[nt][ks][0], kf[nt][ks][1]);
            }
        #pragma unroll
        for (int mt = 0; mt < 2; mt++)
            #pragma unroll
            for (int h = 0; h < 2; h++) {
                int q = m0 + mt * 16 + gId + 8 * h;
                #pragma unroll
                for (int nt = 0; nt < 4; nt++) {
                    float2 bv = *(const float2*)&bias[(size_t)q * WINN + jc + nt * 8 + 2 * tig];
                    s[mt][nt][2*h]   = s[mt][nt][2*h]   * scale + bv.x;
                    s[mt][nt][2*h+1] = s[mt][nt][2*h+1] * scale + bv.y;
                }
            }
        float co2[2][2];
        #pragma unroll
        for (int mt = 0; mt < 2; mt++)
            #pragma unroll
            for (int h = 0; h < 2; h++) {
                float rm = -1e30f;
                #pragma unroll
                for (int nt = 0; nt < 4; nt++)
                    rm = fmaxf(rm, fmaxf(s[mt][nt][2*h], s[mt][nt][2*h+1]));
                rm = fmaxf(rm, __shfl_xor_sync(0xffffffffu, rm, 1));
                rm = fmaxf(rm, __shfl_xor_sync(0xffffffffu, rm, 2));
                float mn = fmaxf(mrow[mt][h], rm);
                float co = __expf(mrow[mt][h] - mn);
                mrow[mt][h] = mn;
                float rs = 0.f;
                #pragma unroll
                for (int nt = 0; nt < 4; nt++) {
                    float e0 = __expf(s[mt][nt][2*h]   - mn);
                    float e1 = __expf(s[mt][nt][2*h+1] - mn);
                    s[mt][nt][2*h] = e0; s[mt][nt][2*h+1] = e1;
                    rs += e0 + e1;
                }
                rs += __shfl_xor_sync(0xffffffffu, rs, 1);
                rs += __shfl_xor_sync(0xffffffffu, rs, 2);
                lrow[mt][h] = lrow[mt][h] * co + rs;
                co2[mt][h] = co;
            }
        #pragma unroll
        for (int mt = 0; mt < 2; mt++)
            #pragma unroll
            for (int vn = 0; vn < 4; vn++)
                #pragma unroll
                for (int i = 0; i < 4; i++) o[mt][vn][i] *= co2[mt][i >> 1];
        #pragma unroll
        for (int ks = 0; ks < 2; ks++) {
            unsigned a[2][4];
            #pragma unroll
            for (int mt = 0; mt < 2; mt++) {
                a[mt][0] = bf2pack(s[mt][2*ks][0],   s[mt][2*ks][1]);
                a[mt][1] = bf2pack(s[mt][2*ks][2],   s[mt][2*ks][3]);
                a[mt][2] = bf2pack(s[mt][2*ks+1][0], s[mt][2*ks+1][1]);
                a[mt][3] = bf2pack(s[mt][2*ks+1][2], s[mt][2*ks+1][3]);
            }
            #pragma unroll
            for (int vn = 0; vn < 4; vn++) {
                const unsigned short* vp = Vt + (vn * 8 + gId) * VPITCH + jc + ks * 16 + 2 * tig;
                unsigned b0 = *(const unsigned*)vp;
                unsigned b1 = *(const unsigned*)(vp + 8);
                #pragma unroll
                for (int mt = 0; mt < 2; mt++)
                    mma_bf(o[mt][vn], a[mt], b0, b1);
            }
        }
    }
    #pragma unroll
    for (int mt = 0; mt < 2; mt++)
        #pragma unroll
        for (int h = 0; h < 2; h++) {
            float inv = 1.f / lrow[mt][h];
            int row = m0 + mt * 16 + gId + 8 * h;
            int ny = (wy * WS + (row >> 4)) * WW + wx * WS + (row & 15);
            unsigned short* obase = yout + ((size_t)(b * NTOK + ny)) * DIMC + hh * HD;
            #pragma unroll
            for (int vn = 0; vn < 4; vn++) {
                int vd = vn * 8 + 2 * tig;
                if (vd < HD)
                    *(unsigned*)(obase + vd) =
                        bf2pack(o[mt][vn][2*h] * inv, o[mt][vn][2*h+1] * inv);
            }
        }
}

// ---------------------------------------------------------------------------
// Gather per-token dictionary features into hc[:, 360:424] (fp32)
// ---------------------------------------------------------------------------
__global__ void gathertd_kernel(const float* __restrict__ tdproj, const int* __restrict__ tkid,
                                float* __restrict__ hc) {
    int e = blockIdx.x * blockDim.x + threadIdx.x;
    if (e < ROWS * DTD) {
        int r = e >> 6, j = e & 63;
        int b = r >> 12;
        hc[(size_t)r * CFF + MLP_HID + j] = tdproj[((size_t)b * MTOK + tkid[r]) * DTD + j];
    }
}

// ---------------------------------------------------------------------------
// Depthwise 5x5 conv + GELU + residual; fp32 hc in, bf16 hc2 out.
// ---------------------------------------------------------------------------
#define DWCH 8
__global__ void dwconv_kernel(const float* __restrict__ hc, const float* __restrict__ w,
                              const float* __restrict__ bias, unsigned short* __restrict__ hc2) {
    __shared__ float smd[20 * 20 * DWCH];
    __shared__ float wsm[25][DWCH];
    __shared__ float bsm[DWCH];
    int tid = threadIdx.x;
    int c0 = blockIdx.y * DWCH;
    int b  = blockIdx.z;
    int tileY = (blockIdx.x >> 2) * 16, tileX = (blockIdx.x & 3) * 16;
    if (tid < 200) { int t5 = tid % 25, j = tid / 25; wsm[t5][j] = w[(c0 + j) * 25 + t5]; }
    if (tid < DWCH) bsm[tid] = bias[c0 + tid];
    for (int i = tid; i < 800; i += 256) {
        int cell = i >> 1, half = i & 1;
        int cy = cell / 20, cx = cell % 20;
        int gy = tileY + cy - 2, gx = tileX + cx - 2;
        float4 v = {0.f, 0.f, 0.f, 0.f};
        if (gy >= 0 && gy < 64 && gx >= 0 && gx < 64)
            v = *(const float4*)&hc[(((size_t)b << 12) + (gy << 6) + gx) * CFF + c0 + half * 4];
        *(float4*)&smd[cell * 8 + half * 4] = v;
    }
    __syncthreads();
    int ty = tid >> 4, tx = tid & 15;
    float acc[DWCH];
    #pragma unroll
    for (int j = 0; j < DWCH; j++) acc[j] = 0.f;
    #pragma unroll
    for (int ky = 0; ky < 5; ky++) {
        #pragma unroll
        for (int kx = 0; kx < 5; kx++) {
            const float* cp = &smd[((ty + ky) * 20 + tx + kx) * 8];
            float4 a0 = *(const float4*)cp;
            float4 a1 = *(const float4*)(cp + 4);
            int t5 = ky * 5 + kx;
            acc[0] += a0.x * wsm[t5][0];
            acc[1] += a0.y * wsm[t5][1];
            acc[2] += a0.z * wsm[t5][2];
            acc[3] += a0.w * wsm[t5][3];
            acc[4] += a1.x * wsm[t5][4];
            acc[5] += a1.y * wsm[t5][5];
            acc[6] += a1.z * wsm[t5][6];
            acc[7] += a1.w * wsm[t5][7];
        }
    }
    const float* ctr = &smd[((ty + 2) * 20 + tx + 2) * 8];
    size_t idx = (((size_t)b << 12) + ((size_t)(tileY + ty) << 6) + (tileX + tx)) * CFF + c0;
    float o[8];
    #pragma unroll
    for (int j = 0; j < 8; j++) o[j] = ctr[j] + gelu_exact(acc[j] + bsm[j]);
    uint4 pk;
    pk.x = bf2pack(o[0], o[1]);
    pk.y = bf2pack(o[2], o[3]);
    pk.z = bf2pack(o[4], o[5]);
    pk.w = bf2pack(o[6], o[7]);
    *(uint4*)&hc2[idx] = pk;
}

// ---------------------------------------------------------------------------
// Launch: two-stream DAG; qkv now bf16 end-to-end.
// ---------------------------------------------------------------------------
extern "C" void kernel_launch(void* const* d_in, const int* in_sizes, int n_in,
                              void* d_out, int out_size) {
    const float* x        = (const float*)d_in[0];
    const float* td       = (const float*)d_in[1];
    const float* n1g      = (const float*)d_in[2];
    const float* n1b      = (const float*)d_in[3];
    const float* wqkv_w   = (const float*)d_in[4];
    const float* wqkv_b   = (const float*)d_in[5];
    const float* atd_wq_w = (const float*)d_in[6];
    const float* atd_wq_b = (const float*)d_in[7];
    const float* atd_wk_w = (const float*)d_in[8];
    const float* atd_wk_b = (const float*)d_in[9];
    const float* atd_wv_w = (const float*)d_in[10];
    const float* atd_wv_b = (const float*)d_in[11];
    const float* atd_sc   = (const float*)d_in[12];
    const float* aca_w    = (const float*)d_in[13];
    const float* aca_b    = (const float*)d_in[14];
    const float* win_rpb  = (const float*)d_in[15];
    const float* win_w    = (const float*)d_in[16];
    const float* win_b    = (const float*)d_in[17];
    const float* fctd_w   = (const float*)d_in[18];
    const float* fctd_b   = (const float*)d_in[19];
    const float* fc1_w    = (const float*)d_in[20];
    const float* fc1_b    = (const float*)d_in[21];
    const float* dw_w     = (const float*)d_in[22];
    const float* dw_b     = (const float*)d_in[23];
    const float* fc2_w    = (const float*)d_in[24];
    const float* fc2_b    = (const float*)d_in[25];
    const float* n2g      = (const float*)d_in[26];
    const float* n2b      = (const float*)d_in[27];
    const int*   rpi      = (const int*)d_in[28];
    float* out = (float*)d_out;

    float *qatd, *kkn, *tdpr, *xsum, *hc;
    unsigned short *xn, *qkv, *x2n, *yaca, *ywin, *patd, *hc2, *vvt, *wt;
    int *tkid, *sidx;
    cudaGetSymbolAddress((void**)&xn,   g_xn);
    cudaGetSymbolAddress((void**)&qkv,  g_qkv);
    cudaGetSymbolAddress((void**)&qatd, g_qatd);
    cudaGetSymbolAddress((void**)&kkn,  g_kkn);
    cudaGetSymbolAddress((void**)&vvt,  g_vvt);
    cudaGetSymbolAddress((void**)&tdpr, g_tdpr);
    cudaGetSymbolAddress((void**)&patd, g_patd);
    cudaGetSymbolAddress((void**)&yaca, g_yaca);
    cudaGetSymbolAddress((void**)&ywin, g_ywin);
    cudaGetSymbolAddress((void**)&xsum, g_xsum);
    cudaGetSymbolAddress((void**)&x2n,  g_x2n);
    cudaGetSymbolAddress((void**)&hc,   g_hc);
    cudaGetSymbolAddress((void**)&hc2,  g_hc2);
    cudaGetSymbolAddress((void**)&tkid, g_tkid);
    cudaGetSymbolAddress((void**)&sidx, g_sidx);
    cudaGetSymbolAddress((void**)&wt,   g_wt);

    static cudaStream_t s1 = nullptr;
    static cudaEvent_t eRoot, eLn1, eConvw, eWbias, eQkv, eAcmsa, eGath;
    if (!s1) {
        cudaStreamCreateWithFlags(&s1, cudaStreamNonBlocking);
        cudaEventCreateWithFlags(&eRoot,  cudaEventDisableTiming);
        cudaEventCreateWithFlags(&eLn1,   cudaEventDisableTiming);
        cudaEventCreateWithFlags(&eConvw, cudaEventDisableTiming);
        cudaEventCreateWithFlags(&eWbias, cudaEventDisableTiming);
        cudaEventCreateWithFlags(&eQkv,   cudaEventDisableTiming);
        cudaEventCreateWithFlags(&eAcmsa, cudaEventDisableTiming);
        cudaEventCreateWithFlags(&eGath,  cudaEventDisableTiming);
        cudaFuncSetAttribute(winattn_tc, cudaFuncAttributeMaxDynamicSharedMemorySize, WSMEM);
    }

    // ---- fork side stream from main ----
    cudaEventRecord(eRoot, 0);
    cudaStreamWaitEvent(s1, eRoot, 0);

    // ---- side stream: prologue kernels ----
    convw_all<<<(S_TOT + 255)/256, 256, 0, s1>>>(wqkv_w, aca_w, win_w, fc1_w, fc2_w, wt);
    cudaEventRecord(eConvw, s1);
    wbias_kernel<<<WINN*WINN/256, 256, 0, s1>>>(rpi, win_rpb);
    cudaEventRecord(eWbias, s1);
    dict_kernel<<<BATCH*MTOK, 256, 0, s1>>>(td, atd_wk_w, atd_wk_b, atd_wv_w, atd_wv_b,
                                            fctd_w, fctd_b, kkn, vvt, tdpr);

    // ---- main stream: LN1 (+ fused q_atd) ----
    ln_kernel<<<ROWS/8, 256>>>(x, n1g, n1b, xn, atd_wq_w, atd_wq_b, qatd);
    cudaEventRecord(eLn1, 0);

    // main: qkv GEMM -> bf16 (needs convw)
    cudaStreamWaitEvent(0, eConvw, 0);
    gemm_bf<<<dim3(9, ROWS/128), 256>>>(xn, wt + WT_QKV, DIMC, nullptr, nullptr, 0,
                                        nullptr, nullptr, 0, 0,
                                        wqkv_b, nullptr, nullptr,
                                        nullptr, qkv, ROWS, QKVW, QKVW, 0);
    cudaEventRecord(eQkv, 0);

    // main: tensor-core window attention (needs qkv + wbias)
    cudaStreamWaitEvent(0, eWbias, 0);
    winattn_tc<<<NWIN*HEADS, 256, WSMEM>>>(qkv, ywin);

    // ---- side stream: ATD chain (needs ln1; acmsa needs qkv) ----
    cudaStreamWaitEvent(s1, eLn1, 0);
    atd_kernel<<<ROWS/8, 256, 0, s1>>>(qatd, kkn, atd_sc, patd, tkid);
    sortscatter_kernel<<<BATCH*MTOK, 256, 0, s1>>>(tkid, sidx);
    cudaStreamWaitEvent(s1, eQkv, 0);
    acmsa_tc<<<BATCH*NG*HEADS, 128, 0, s1>>>(qkv, sidx, yaca);
    cudaEventRecord(eAcmsa, s1);
    gathertd_kernel<<<ROWS*DTD/256, 256, 0, s1>>>(tdpr, tkid, hc);
    cudaEventRecord(eGath, s1);

    // ---- main stream: join acmsa branch, fused residual GEMM ----
    cudaStreamWaitEvent(0, eAcmsa, 0);
    gemm_bf<<<dim3(3, ROWS/128), 256>>>(yaca, wt + WT_ACA, DIMC, ywin, wt + WT_WIN, DIMC,
                                        patd, vvt, (long)DIMC*MTOK, MTOK,
                                        aca_b, win_b, x,
                                        xsum, nullptr, ROWS, DIMC, DIMC, 0);
    ln_kernel<<<ROWS/8, 256>>>(xsum, n2g, n2b, x2n, nullptr, nullptr, nullptr);
    gemm_bf<<<dim3(6, ROWS/128), 256>>>(x2n, wt + WT_FC1, DIMC, nullptr, nullptr, 0,
                                        nullptr, nullptr, 0, 0,
                                        fc1_b, nullptr, nullptr,
                                        hc, nullptr, ROWS, MLP_HID, CFF, 1);
    cudaStreamWaitEvent(0, eGath, 0);
    dwconv_kernel<<<dim3(16, CFF/DWCH, BATCH), 256>>>(hc, dw_w, dw_b, hc2);
    gemm_bf<<<dim3(3, ROWS/128), 256>>>(hc2, wt + WT_FC2, CFF, nullptr, nullptr, 0,
                                        nullptr, nullptr, 0, 0,
                                        fc2_b, nullptr, xsum,
                                        out, nullptr, ROWS, DIMC, DIMC, 0);
}